// round 11
// baseline (speedup 1.0000x reference)
#include <cuda_runtime.h>
#include <math.h>

// Problem constants
#define EE  4      // experts
#define BB  32     // batch
#define HH  7
#define LL  49     // H*W
#define DD  512    // dim
#define C2  1024   // 2*dim
#define RR  32     // DT_RANK
#define NS  16     // N_STATE
#define KDn 4      // directions
#define NSLOT (BB*2)   // 64 selected (b, expert) slots

// ---------------- scratch (device globals; no allocation allowed) ----------
__device__ float g_v [NSLOT*LL*DD];          // conv output v, slot-indexed (v-space)
__device__ float g_z [NSLOT*LL*DD];          // z half of in_proj, slot-indexed
__device__ float g_ys[NSLOT*KDn*LL*DD];      // scan outputs (v-space!)
__device__ float g_dt[NSLOT*KDn*LL*DD];      // softplus(dt) (v-space)
__device__ float g_Bm[NSLOT*KDn*LL*NS];      // B (v-space)
__device__ float g_Cm[NSLOT*KDn*LL*NS];      // C (v-space)
__device__ float g_xpwT[EE*DD*256];          // transposed x_proj_w: [e][d][k*64+c]
__device__ float g_dtwT[EE*KDn*RR*DD];       // transposed dt_proj_w: [e][k][r][d]
__device__ float g_raw[BB*EE];
__device__ float g_aux;
__device__ int   g_topi[NSLOT];              // slot s -> expert  (b = s>>1)
__device__ float g_topv[NSLOT];              // slot s -> gate coeff
__device__ float g_allout[NSLOT*DD];         // slot-indexed expert outputs

// ---------------- f32x2 packed FMA helpers (sm_103a) -----------------------
__device__ __forceinline__ unsigned long long pk2(float lo, float hi){
    unsigned long long r;
    asm("mov.b64 %0, {%1, %2};" : "=l"(r) : "f"(lo), "f"(hi));
    return r;
}
__device__ __forceinline__ void fma2(unsigned long long& d, unsigned long long a, unsigned long long b){
    asm("fma.rn.f32x2 %0, %1, %2, %0;" : "+l"(d) : "l"(a), "l"(b));
}
__device__ __forceinline__ void upk2(unsigned long long v, float& lo, float& hi){
    asm("mov.b64 {%0, %1}, %2;" : "=f"(lo), "=f"(hi) : "l"(v));
}
__device__ __forceinline__ float ex2f(float x){
    float r; asm("ex2.approx.f32 %0, %1;" : "=f"(r) : "f"(x)); return r;
}
__device__ __forceinline__ float lg2f(float x){
    float r; asm("lg2.approx.f32 %0, %1;" : "=f"(r) : "f"(x)); return r;
}

// ---------------- K0a: transpose x_proj_w -> g_xpwT [e][d][k*64+c] ---------
__global__ void k_wt(const float* __restrict__ xpw_){
    int row = blockIdx.x;            // ((e*4+k)*64 + c)
    int e  = row >> 8;
    int kc = row & 255;              // k*64+c
    const float* src = xpw_ + (size_t)row*DD;
    float* dst = g_xpwT + (size_t)e*DD*256 + kc;
    for (int d = threadIdx.x; d < DD; d += 128) dst[(size_t)d*256] = src[d];
}

// ---------------- K0b: transpose dt_proj_w -> g_dtwT [e][k][r][d] ----------
__global__ void k_wt2(const float* __restrict__ dtw_){
    int ek = blockIdx.x;             // e*4+k
    const float* src = dtw_ + (size_t)ek*DD*RR;
    float* dst = g_dtwT + (size_t)ek*DD*RR;
    for (int i = threadIdx.x; i < DD*RR; i += 512){
        int d = i >> 5, r = i & 31;
        dst[r*DD + d] = src[i];
    }
}

// ---------------- K1: gate logits + softmax per batch ----------------------
__global__ void k_gate(const float* __restrict__ x, const float* __restrict__ wg,
                       const float* __restrict__ bg){
    int b = blockIdx.x, tid = threadIdx.x;           // 512 threads, tid = channel
    const float* xb = x + (size_t)b*LL*DD + tid;
    float s = 0.f;
    #pragma unroll 7
    for (int l = 0; l < LL; l++) s += xb[l*DD];
    s *= (1.f/49.f);
    float p0 = s*wg[tid*EE+0], p1 = s*wg[tid*EE+1];
    float p2 = s*wg[tid*EE+2], p3 = s*wg[tid*EE+3];
    #pragma unroll
    for (int o = 16; o; o >>= 1){
        p0 += __shfl_xor_sync(0xffffffffu, p0, o);
        p1 += __shfl_xor_sync(0xffffffffu, p1, o);
        p2 += __shfl_xor_sync(0xffffffffu, p2, o);
        p3 += __shfl_xor_sync(0xffffffffu, p3, o);
    }
    __shared__ float sp[16][4];
    int w = tid >> 5, lane = tid & 31;
    if (lane == 0){ sp[w][0]=p0; sp[w][1]=p1; sp[w][2]=p2; sp[w][3]=p3; }
    __syncthreads();
    if (tid == 0){
        float lg[4];
        for (int e = 0; e < 4; e++){
            float a = bg[e];
            for (int ww = 0; ww < 16; ww++) a += sp[ww][e];
            lg[e] = a;
        }
        float m = fmaxf(fmaxf(lg[0],lg[1]), fmaxf(lg[2],lg[3]));
        float ex[4], se = 0.f;
        for (int e = 0; e < 4; e++){ ex[e] = expf(lg[e]-m); se += ex[e]; }
        for (int e = 0; e < 4; e++) g_raw[b*4+e] = ex[e]/se;
    }
}

// ---------------- K2: top-k, mask, denom, aux loss, gate scores ------------
__global__ void k_gatefin(){
    __shared__ float sraw[32][4];
    __shared__ float smask[32][4];
    __shared__ float sden[4];
    int b = threadIdx.x;  // 32 threads
    float r[4];
    #pragma unroll
    for (int e = 0; e < 4; e++){ r[e] = g_raw[b*4+e]; sraw[b][e] = r[e]; }
    int i0 = 0; float m0 = r[0];
    #pragma unroll
    for (int e = 1; e < 4; e++) if (r[e] > m0){ m0 = r[e]; i0 = e; }
    int i1 = -1; float m1 = -1e30f;
    #pragma unroll
    for (int e = 0; e < 4; e++) if (e != i0 && r[e] > m1){ m1 = r[e]; i1 = e; }
    #pragma unroll
    for (int e = 0; e < 4; e++) smask[b][e] = (e==i0 || e==i1) ? 1.f : 0.f;
    __syncthreads();
    if (b == 0){
        float aux = 0.f;
        for (int e = 0; e < 4; e++){
            float ds = 0.f, imp = 0.f, ld = 0.f;
            for (int bb = 0; bb < 32; bb++){
                ds  += sraw[bb][e]*smask[bb][e];
                imp += sraw[bb][e];
                ld  += smask[bb][e];
            }
            sden[e] = ds + 1e-6f;
            imp *= (1.f/32.f); ld *= (1.f/32.f);
            aux += (ld-imp)*(ld-imp);
        }
        g_aux = 0.01f * aux * 0.25f;
    }
    __syncthreads();
    const float cap = 40.f;   // int(1.25*32)
    float s0 = r[i0]*cap/sden[i0];
    float s1 = r[i1]*cap/sden[i1];
    int a0 = i0, a1 = i1; float v0 = s0, v1 = s1;
    if (v1 > v0 || (v1 == v0 && a1 < a0)){
        int t = a0; a0 = a1; a1 = t;
        float tv = v0; v0 = v1; v1 = tv;
    }
    g_topi[b*2] = a0; g_topi[b*2+1] = a1;
    g_topv[b*2] = v0; g_topv[b*2+1] = v1;
}

// ---------------- K3: in_proj GEMM + fused depthwise conv -> g_v -----------
// grid (64 slots, 2 roles) x 512 threads. sx TRANSPOSED in smem (stride 54).
// Thread tile 8 cols x (8|6) l; each xp LDS.64 feeds 8 FFMA2 (crossbar 4x cut).
#define SXS 54
#define IP_SMEM ((DD*SXS + LL*DD)*4)   // 110592 + 100352 = 210944
template<int NP>
__device__ __forceinline__ void ip_phaseA(
    const float* __restrict__ sxT, float* __restrict__ sxin,
    const float* __restrict__ We, const float* __restrict__ bip,
    float* __restrict__ zout, int role, int lbase, int c0)
{
    unsigned long long acc[8][NP];
    #pragma unroll
    for (int c = 0; c < 8; c++)
        #pragma unroll
        for (int p = 0; p < NP; p++) acc[c][p] = 0ull;

    float4 wa0 = *(const float4*)(We);
    float4 wa1 = *(const float4*)(We + 4);
    #pragma unroll 1
    for (int kk = 0; kk < DD; kk++){
        float4 wb0, wb1;
        if (kk + 1 < DD){
            wb0 = *(const float4*)(We + (size_t)(kk+1)*C2);
            wb1 = *(const float4*)(We + (size_t)(kk+1)*C2 + 4);
        }
        const float* xr = sxT + kk*SXS + lbase;
        unsigned long long xp[NP];
        #pragma unroll
        for (int p = 0; p < NP; p++)
            xp[p] = *(const unsigned long long*)(xr + 2*p);
        float wv[8];
        *(float4*)(wv)   = wa0;
        *(float4*)(wv+4) = wa1;
        #pragma unroll
        for (int c = 0; c < 8; c++){
            unsigned long long wd = pk2(wv[c], wv[c]);
            #pragma unroll
            for (int p = 0; p < NP; p++) fma2(acc[c][p], wd, xp[p]);
        }
        wa0 = wb0; wa1 = wb1;
    }
    // epilogue: bias + store
    float4 b0 = *(const float4*)(bip);
    float4 b1 = *(const float4*)(bip + 4);
    float bs[8];
    *(float4*)(bs)   = b0;
    *(float4*)(bs+4) = b1;
    float* dst = (role == 0) ? sxin : zout;
    #pragma unroll
    for (int p = 0; p < NP; p++){
        int l0 = lbase + 2*p, l1 = l0 + 1;
        float lo[8], hi[8];
        #pragma unroll
        for (int c = 0; c < 8; c++) upk2(acc[c][p], lo[c], hi[c]);
        if (l0 < LL){
            float4 o0 = make_float4(lo[0]+bs[0], lo[1]+bs[1], lo[2]+bs[2], lo[3]+bs[3]);
            float4 o1 = make_float4(lo[4]+bs[4], lo[5]+bs[5], lo[6]+bs[6], lo[7]+bs[7]);
            *(float4*)(dst + (size_t)l0*DD + c0)     = o0;
            *(float4*)(dst + (size_t)l0*DD + c0 + 4) = o1;
        }
        if (l1 < LL){
            float4 o0 = make_float4(hi[0]+bs[0], hi[1]+bs[1], hi[2]+bs[2], hi[3]+bs[3]);
            float4 o1 = make_float4(hi[4]+bs[4], hi[5]+bs[5], hi[6]+bs[6], hi[7]+bs[7]);
            *(float4*)(dst + (size_t)l1*DD + c0)     = o0;
            *(float4*)(dst + (size_t)l1*DD + c0 + 4) = o1;
        }
    }
}

__global__ void __launch_bounds__(512, 1)
k_inproj(const float* __restrict__ x, const float* __restrict__ Wi,
         const float* __restrict__ bi, const float* __restrict__ cw,
         const float* __restrict__ cb){
    extern __shared__ float sm_[];
    float* sxT  = sm_;             // [DD][SXS]
    float* sxin = sm_ + DD*SXS;    // [LL][DD] (role 0 only)
    int s = blockIdx.x, role = blockIdx.y, tid = threadIdx.x;
    int b = s >> 1;
    int e = g_topi[s];
    const float* xb = x + (size_t)b*LL*DD;
    // load + transpose x
    for (int i = tid; i < LL*DD; i += 512){
        int l = i >> 9, d = i & 511;
        sxT[d*SXS + l] = xb[i];
    }
    {
        int d = tid;
        #pragma unroll
        for (int l = 49; l < SXS; l++) sxT[d*SXS + l] = 0.f;
    }
    __syncthreads();

    int cg = tid & 63, lg = tid >> 6;
    int c0 = cg*8;
    const float* We  = Wi + (size_t)e*DD*C2 + role*DD + c0;
    const float* bip = bi + e*C2 + role*DD + c0;
    float* zout = g_z + (size_t)s*LL*DD;
    if (lg < 3){
        ip_phaseA<4>(sxT, sxin, We, bip, zout, role, lg*8, c0);
    } else {
        ip_phaseA<3>(sxT, sxin, We, bip, zout, role, 24 + (lg-3)*6, c0);
    }
    if (role != 0) return;
    __syncthreads();
    // ---- depthwise 3x3 conv + silu -> g_v (single write); d = tid ----
    float* vout = g_v + (size_t)s*LL*DD;
    {
        int d = tid;
        float w9[9];
        #pragma unroll
        for (int t = 0; t < 9; t++) w9[t] = cw[(e*DD+d)*9 + t];
        float bias = cb[e*DD+d];
        float row[3][7];
        #pragma unroll
        for (int j = 0; j < 7; j++){
            row[0][j] = sxin[(0*7+j)*DD + d];
            row[1][j] = sxin[(1*7+j)*DD + d];
        }
        #pragma unroll
        for (int i = 0; i < 7; i++){
            if (i < 6){
                #pragma unroll
                for (int j = 0; j < 7; j++)
                    row[(i+1)%3][j] = sxin[((i+1)*7+j)*DD + d];
            }
            const float* rm = (i > 0) ? row[(i-1)%3] : nullptr;
            const float* rc = row[i%3];
            const float* rp = (i < 6) ? row[(i+1)%3] : nullptr;
            #pragma unroll
            for (int j = 0; j < 7; j++){
                float a = bias;
                #pragma unroll
                for (int dj = 0; dj < 3; dj++){
                    int jj = j + dj - 1;
                    if (jj < 0 || jj > 6) continue;
                    if (i > 0) a += rm[jj]*w9[0*3+dj];
                    a += rc[jj]*w9[1*3+dj];
                    if (i < 6) a += rp[jj]*w9[2*3+dj];
                }
                float v = a / (1.f + __expf(-a));   // silu
                vout[(i*7+j)*DD + d] = v;
            }
        }
    }
}

// ---------------- K5a: merged x_dbl GEMM (all 4 dirs) + dt_proj ------------
// grid (64 slots, 2 roles) x 512 threads. Thread tile 4 cols x (4|2) l.
#define SX2 54
#define XD_SMEM ((DD*SX2 + 128*SX2)*4)   // 110592 + 27648 = 138240
template<int NP>
__device__ __forceinline__ void xd_phaseA(
    const float* __restrict__ vT, float* __restrict__ sY,
    const float* __restrict__ Wp, int lbase, int cg)
{
    unsigned long long acc[4][NP];
    #pragma unroll
    for (int c = 0; c < 4; c++)
        #pragma unroll
        for (int p = 0; p < NP; p++) acc[c][p] = 0ull;
    float4 wa = *(const float4*)(Wp);
    #pragma unroll 2
    for (int kk = 0; kk < DD; kk++){
        float4 wb;
        if (kk + 1 < DD) wb = *(const float4*)(Wp + (size_t)(kk+1)*256);
        const float* xr = vT + kk*SX2 + lbase;
        unsigned long long xp[NP];
        #pragma unroll
        for (int p = 0; p < NP; p++)
            xp[p] = *(const unsigned long long*)(xr + 2*p);
        float wv[4];
        *(float4*)(wv) = wa;
        #pragma unroll
        for (int c = 0; c < 4; c++){
            unsigned long long wd = pk2(wv[c], wv[c]);
            #pragma unroll
            for (int p = 0; p < NP; p++) fma2(acc[c][p], wd, xp[p]);
        }
        wa = wb;
    }
    // epilogue -> sY
    #pragma unroll
    for (int c = 0; c < 4; c++){
        int rowi = cg*4 + c;
        #pragma unroll
        for (int p = 0; p < NP; p++){
            float lo, hi;
            upk2(acc[c][p], lo, hi);
            sY[rowi*SX2 + lbase + 2*p]     = lo;
            sY[rowi*SX2 + lbase + 2*p + 1] = hi;
        }
    }
}

__global__ void __launch_bounds__(512, 1)
k_xdbl(const float* __restrict__ dtb_){
    extern __shared__ float sm[];
    float* vT = sm;                  // [DD][SX2]
    float* sY = sm + DD*SX2;         // [128][SX2]  Y rows for this role
    int s = blockIdx.x, role = blockIdx.y, tid = threadIdx.x;
    int e = g_topi[s];

    // load + transpose v
    const float* vsrc = g_v + (size_t)s*LL*DD;
    for (int i = tid; i < LL*DD; i += 512){
        int l = i >> 9, d = i & 511;
        vT[d*SX2 + l] = vsrc[i];
    }
    {
        int d = tid;
        #pragma unroll
        for (int l = 49; l < SX2; l++) vT[d*SX2 + l] = 0.f;
    }
    __syncthreads();

    // ---- phase A: Y[kc][l] = sum_d v[l][d] * xpwT[e][d][kc] ----
    int cg = tid & 31, lg = tid >> 5;            // 32 cgroups x 16 lgroups
    int kc0 = role*128 + cg*4;
    const float* Wp = g_xpwT + (size_t)e*DD*256 + kc0;
    if (lg < 11){
        xd_phaseA<2>(vT, sY, Wp, lg*4, cg);
    } else {
        xd_phaseA<1>(vT, sY, Wp, 44 + (lg-11)*2, cg);
    }
    __syncthreads();

    // ---- write B/C for this role's 2 directions ----
    for (int i = tid; i < 2*LL*NS; i += 512){
        int kloc = i / (LL*NS);
        int rem  = i - kloc*LL*NS;
        int l = rem >> 4, n = rem & 15;
        int k = role*2 + kloc;
        g_Bm[((size_t)(s*KDn + k)*LL + l)*NS + n] = sY[(kloc*64 + 32 + n)*SX2 + l];
        g_Cm[((size_t)(s*KDn + k)*LL + l)*NS + n] = sY[(kloc*64 + 48 + n)*SX2 + l];
    }

    // ---- dt_proj + softplus for the role's 2 directions; thread = dd ----
    int dd = tid;
    const float L2E = 1.44269504088896f;
    const float LN2 = 0.69314718055995f;
    #pragma unroll 1
    for (int kloc = 0; kloc < 2; kloc++){
        int k = role*2 + kloc;
        float bias = dtb_[(e*KDn + k)*DD + dd];
        // coalesced transposed dtw loads
        float wreg[32];
        {
            const float* wt = g_dtwT + (size_t)(e*KDn + k)*DD*RR + dd;
            #pragma unroll
            for (int r = 0; r < RR; r++) wreg[r] = wt[(size_t)r*DD];
        }
        unsigned long long acc[26];
        unsigned long long binit = pk2(bias, bias);
        #pragma unroll
        for (int t = 0; t < 26; t++) acc[t] = binit;
        const float* sb = sY + (kloc*64)*SX2;
        #pragma unroll 4
        for (int r = 0; r < RR; r++){
            unsigned long long wd = pk2(wreg[r], wreg[r]);
            const float* srow = sb + r*SX2;
            #pragma unroll
            for (int t = 0; t < 26; t++){
                unsigned long long xp = *(const unsigned long long*)(srow + 2*t);
                fma2(acc[t], wd, xp);
            }
        }
        float* dtout = g_dt + (size_t)(s*KDn + k)*LL*DD + dd;
        #pragma unroll
        for (int t = 0; t < 26; t++){
            float a_lo, a_hi;
            upk2(acc[t], a_lo, a_hi);
            int l0 = 2*t, l1 = 2*t + 1;
            if (l0 < LL){
                float dtv = fmaxf(a_lo, 0.f) + LN2*lg2f(1.f + ex2f(-fabsf(a_lo)*L2E));
                dtout[l0*DD] = dtv;
            }
            if (l1 < LL){
                float dtv = fmaxf(a_hi, 0.f) + LN2*lg2f(1.f + ex2f(-fabsf(a_hi)*L2E));
                dtout[l1*DD] = dtv;
            }
        }
    }
}

// ---------------- K5b: selective scan (v-space, permuted indexing) ---------
// grid = 256 blocks (s,k), 512 threads, thread = channel dd.
__global__ void __launch_bounds__(512, 2)
k_scan(const float* __restrict__ alog_, const float* __restrict__ ds_){
    __shared__ float sB[LL*NS];
    __shared__ float sC[LL*NS];
    __shared__ int   sPerm[LL];
    int idx = blockIdx.x;
    int k = idx & 3, s = idx >> 2;
    int e = g_topi[s];
    int dd = threadIdx.x;
    size_t skbase = (size_t)(s*KDn + k);
    {
        const float* Bg = g_Bm + skbase*LL*NS;
        const float* Cg = g_Cm + skbase*LL*NS;
        for (int i = dd; i < LL*NS; i += 512){ sB[i] = Bg[i]; sC[i] = Cg[i]; }
    }
    if (dd < LL){
        int t = dd;
        int tt = (k & 1) ? (48 - t) : t;
        int lsrc = (k >= 2) ? ((tt % 7)*7 + tt/7) : tt;
        sPerm[t] = lsrc;
    }
    float A[NS];
    {
        const float4* al = (const float4*)(alog_ + ((size_t)((e*KDn+k)*DD) + dd)*NS);
        const float L2E = 1.44269504088896f;
        #pragma unroll
        for (int q = 0; q < 4; q++){
            float4 v = al[q];
            A[q*4+0] = -__expf(v.x)*L2E; A[q*4+1] = -__expf(v.y)*L2E;
            A[q*4+2] = -__expf(v.z)*L2E; A[q*4+3] = -__expf(v.w)*L2E;
        }
    }
    float Dd = ds_[(e*KDn+k)*DD + dd];
    const float* dtp = g_dt + skbase*LL*DD + dd;
    const float* vp  = g_v  + (size_t)s*LL*DD + dd;
    float*       ysp = g_ys + skbase*LL*DD + dd;
    __syncthreads();
    float h[NS];
    #pragma unroll
    for (int n = 0; n < NS; n++) h[n] = 0.f;
    int lcur = sPerm[0];
    float dtc = dtp[lcur*DD], xvc = vp[lcur*DD];
    #pragma unroll 1
    for (int t = 0; t < LL; t++){
        int lnext = (t < LL-1) ? sPerm[t+1] : 0;
        float dtn = 0.f, xvn = 0.f;
        if (t < LL-1){ dtn = dtp[lnext*DD]; xvn = vp[lnext*DD]; }
        float dx = dtc*xvc;
        const float* Bl = sB + lcur*NS;
        const float* Cl = sC + lcur*NS;
        float y = 0.f;
        #pragma unroll
        for (int n = 0; n < NS; n++){
            h[n] = h[n]*ex2f(dtc*A[n]) + dx*Bl[n];
            y += h[n]*Cl[n];
        }
        ysp[lcur*DD] = y + Dd*xvc;
        lcur = lnext; dtc = dtn; xvc = xvn;
    }
}

// ---------------- block reduction (sum, sumsq) over 512 threads ------------
__device__ __forceinline__ float2 blockReduce2(float a, float b){
    __shared__ float sa[16], sb[16];
    __shared__ float2 res;
    int lane = threadIdx.x & 31, w = threadIdx.x >> 5;
    #pragma unroll
    for (int o = 16; o; o >>= 1){
        a += __shfl_xor_sync(0xffffffffu, a, o);
        b += __shfl_xor_sync(0xffffffffu, b, o);
    }
    __syncthreads();
    if (lane == 0){ sa[w] = a; sb[w] = b; }
    __syncthreads();
    if (w == 0){
        a = (lane < 16) ? sa[lane] : 0.f;
        b = (lane < 16) ? sb[lane] : 0.f;
        #pragma unroll
        for (int o = 8; o; o >>= 1){
            a += __shfl_xor_sync(0xffffffffu, a, o);
            b += __shfl_xor_sync(0xffffffffu, b, o);
        }
        if (lane == 0){ res.x = a; res.y = b; }
    }
    __syncthreads();
    return res;
}

// ---------------- K7: combine directions + LN + silu(z) gate + pool + LN ---
#define CB_SMEM ((LL*DD + 128)*4)
__global__ void __launch_bounds__(512, 1)
k_combine(const float* __restrict__ og_, const float* __restrict__ ob_,
          const float* __restrict__ ng_, const float* __restrict__ nb_){
    extern __shared__ float sv[];        // 49*512 + mu/rs
    float* smu = sv + LL*DD;             // 49
    float* srs = smu + 56;               // 49
    int s = blockIdx.x, d = threadIdx.x;   // 64 slots, 512 threads
    int e = g_topi[s];
    const float* y0 = g_ys + (size_t)(s*KDn + 0)*LL*DD;
    const float* y1 = g_ys + (size_t)(s*KDn + 1)*LL*DD;
    const float* y2 = g_ys + (size_t)(s*KDn + 2)*LL*DD;
    const float* y3 = g_ys + (size_t)(s*KDn + 3)*LL*DD;
    #pragma unroll 2
    for (int l = 0; l < LL; l++){
        int o = l*DD + d;
        sv[o] = y0[o] + y1[o] + y2[o] + y3[o];
    }
    __syncthreads();
    int w = d >> 5, lane = d & 31;
    for (int l = w; l < LL; l += 16){
        float a = 0.f, s2 = 0.f;
        #pragma unroll
        for (int jj = 0; jj < 16; jj++){
            float xv = sv[l*DD + lane + 32*jj];
            a += xv; s2 += xv*xv;
        }
        #pragma unroll
        for (int o = 16; o; o >>= 1){
            a  += __shfl_xor_sync(0xffffffffu, a, o);
            s2 += __shfl_xor_sync(0xffffffffu, s2, o);
        }
        if (lane == 0){
            float mu = a*(1.f/512.f);
            float var = s2*(1.f/512.f) - mu*mu;
            smu[l] = mu;
            srs[l] = rsqrtf(var + 1e-5f);
        }
    }
    __syncthreads();
    float og = og_[e*DD+d], ob = ob_[e*DD+d];
    const float* zrow = g_z + (size_t)s*LL*DD + d;
    float pooled = 0.f;
    #pragma unroll 7
    for (int l = 0; l < LL; l++){
        float v = sv[l*DD + d];
        float yn = (v - smu[l])*srs[l]*og + ob;
        float z = zrow[l*DD];
        pooled += yn * (z / (1.f + __expf(-z)));
    }
    pooled *= (1.f/49.f);
    float2 ss = blockReduce2(pooled, pooled*pooled);
    float mu = ss.x*(1.f/512.f);
    float var = ss.y*(1.f/512.f) - mu*mu;
    float rs = rsqrtf(var + 1e-5f);
    g_allout[s*DD + d] = (pooled - mu)*rs*ng_[e*DD+d] + nb_[e*DD+d];
}

// ---------------- K8: mixture + aux loss output -----------------------------
__global__ void k_mix(float* __restrict__ out, int out_size){
    int b = blockIdx.x, d = threadIdx.x;
    float v0 = g_topv[b*2], v1 = g_topv[b*2+1];
    out[b*DD + d] = v0*g_allout[(b*2)*DD + d] + v1*g_allout[(b*2+1)*DD + d];
    if (b == 0 && d == 0 && out_size > BB*DD) out[BB*DD] = g_aux;
}

// ---------------- launch ----------------------------------------------------
extern "C" void kernel_launch(void* const* d_in, const int* in_sizes, int n_in,
                              void* d_out, int out_size){
    const float* x    = (const float*)d_in[0];
    const float* wg   = (const float*)d_in[1];
    const float* bg   = (const float*)d_in[2];
    const float* ipw  = (const float*)d_in[3];
    const float* ipb  = (const float*)d_in[4];
    const float* cw   = (const float*)d_in[5];
    const float* cb   = (const float*)d_in[6];
    const float* xpw  = (const float*)d_in[7];
    const float* dtw  = (const float*)d_in[8];
    const float* dtb  = (const float*)d_in[9];
    const float* alog = (const float*)d_in[10];
    const float* ds   = (const float*)d_in[11];
    const float* ong  = (const float*)d_in[12];
    const float* onb  = (const float*)d_in[13];
    const float* ng   = (const float*)d_in[14];
    const float* nb   = (const float*)d_in[15];
    float* out = (float*)d_out;

    cudaFuncSetAttribute(k_inproj,  cudaFuncAttributeMaxDynamicSharedMemorySize, IP_SMEM);
    cudaFuncSetAttribute(k_xdbl,    cudaFuncAttributeMaxDynamicSharedMemorySize, XD_SMEM);
    cudaFuncSetAttribute(k_combine, cudaFuncAttributeMaxDynamicSharedMemorySize, CB_SMEM);

    k_wt      <<<EE*KDn*64, 128>>>(xpw);
    k_wt2     <<<EE*KDn, 512>>>(dtw);
    k_gate    <<<32, 512>>>(x, wg, bg);
    k_gatefin <<<1, 32>>>();
    k_inproj  <<<dim3(NSLOT, 2), 512, IP_SMEM>>>(x, ipw, ipb, cw, cb);
    k_xdbl    <<<dim3(NSLOT, 2), 512, XD_SMEM>>>(dtb);
    k_scan    <<<NSLOT*KDn, 512>>>(alog, ds);
    k_combine <<<NSLOT, 512, CB_SMEM>>>(ong, onb, ng, nb);
    k_mix     <<<BB, 512>>>(out, out_size);
}

// round 12
// speedup vs baseline: 1.1467x; 1.1467x over previous
#include <cuda_runtime.h>
#include <math.h>

// Problem constants
#define EE  4      // experts
#define BB  32     // batch
#define HH  7
#define LL  49     // H*W
#define DD  512    // dim
#define C2  1024   // 2*dim
#define RR  32     // DT_RANK
#define NS  16     // N_STATE
#define KDn 4      // directions
#define NSLOT (BB*2)   // 64 selected (b, expert) slots

// ---------------- scratch (device globals; no allocation allowed) ----------
__device__ float g_v [NSLOT*LL*DD];          // conv output v, slot-indexed (v-space)
__device__ float g_z [NSLOT*LL*DD];          // z half of in_proj, slot-indexed
__device__ float g_ys[NSLOT*KDn*LL*DD];      // scan outputs (v-space!)
__device__ float g_dt[NSLOT*KDn*LL*DD];      // softplus(dt) (v-space)
__device__ float g_Bm[NSLOT*KDn*LL*NS];      // B (v-space)
__device__ float g_Cm[NSLOT*KDn*LL*NS];      // C (v-space)
__device__ float g_xpwT[EE*DD*256];          // transposed x_proj_w: [e][d][k*64+c]
__device__ float g_dtwT[EE*KDn*RR*DD];       // transposed dt_proj_w: [e][k][r][d]
__device__ float g_raw[BB*EE];
__device__ float g_aux;
__device__ int   g_topi[NSLOT];              // slot s -> expert  (b = s>>1)
__device__ float g_topv[NSLOT];              // slot s -> gate coeff
__device__ float g_allout[NSLOT*DD];         // slot-indexed expert outputs

// ---------------- f32x2 packed FMA helpers (sm_103a) -----------------------
__device__ __forceinline__ unsigned long long pk2(float lo, float hi){
    unsigned long long r;
    asm("mov.b64 %0, {%1, %2};" : "=l"(r) : "f"(lo), "f"(hi));
    return r;
}
__device__ __forceinline__ void fma2(unsigned long long& d, unsigned long long a, unsigned long long b){
    asm("fma.rn.f32x2 %0, %1, %2, %0;" : "+l"(d) : "l"(a), "l"(b));
}
__device__ __forceinline__ void upk2(unsigned long long v, float& lo, float& hi){
    asm("mov.b64 {%0, %1}, %2;" : "=f"(lo), "=f"(hi) : "l"(v));
}
__device__ __forceinline__ float ex2f(float x){
    float r; asm("ex2.approx.f32 %0, %1;" : "=f"(r) : "f"(x)); return r;
}
__device__ __forceinline__ float lg2f(float x){
    float r; asm("lg2.approx.f32 %0, %1;" : "=f"(r) : "f"(x)); return r;
}

// ---------------- K0a: transpose x_proj_w -> g_xpwT [e][d][k*64+c] ---------
__global__ void k_wt(const float* __restrict__ xpw_){
    int row = blockIdx.x;            // ((e*4+k)*64 + c)
    int e  = row >> 8;
    int kc = row & 255;              // k*64+c
    const float* src = xpw_ + (size_t)row*DD;
    float* dst = g_xpwT + (size_t)e*DD*256 + kc;
    for (int d = threadIdx.x; d < DD; d += 128) dst[(size_t)d*256] = src[d];
}

// ---------------- K0b: transpose dt_proj_w -> g_dtwT [e][k][r][d] ----------
__global__ void k_wt2(const float* __restrict__ dtw_){
    int ek = blockIdx.x;             // e*4+k
    const float* src = dtw_ + (size_t)ek*DD*RR;
    float* dst = g_dtwT + (size_t)ek*DD*RR;
    for (int i = threadIdx.x; i < DD*RR; i += 512){
        int d = i >> 5, r = i & 31;
        dst[r*DD + d] = src[i];
    }
}

// ---------------- K1: gate logits + softmax per batch ----------------------
__global__ void k_gate(const float* __restrict__ x, const float* __restrict__ wg,
                       const float* __restrict__ bg){
    int b = blockIdx.x, tid = threadIdx.x;           // 512 threads, tid = channel
    const float* xb = x + (size_t)b*LL*DD + tid;
    float s = 0.f;
    #pragma unroll 7
    for (int l = 0; l < LL; l++) s += xb[l*DD];
    s *= (1.f/49.f);
    float p0 = s*wg[tid*EE+0], p1 = s*wg[tid*EE+1];
    float p2 = s*wg[tid*EE+2], p3 = s*wg[tid*EE+3];
    #pragma unroll
    for (int o = 16; o; o >>= 1){
        p0 += __shfl_xor_sync(0xffffffffu, p0, o);
        p1 += __shfl_xor_sync(0xffffffffu, p1, o);
        p2 += __shfl_xor_sync(0xffffffffu, p2, o);
        p3 += __shfl_xor_sync(0xffffffffu, p3, o);
    }
    __shared__ float sp[16][4];
    int w = tid >> 5, lane = tid & 31;
    if (lane == 0){ sp[w][0]=p0; sp[w][1]=p1; sp[w][2]=p2; sp[w][3]=p3; }
    __syncthreads();
    if (tid == 0){
        float lg[4];
        for (int e = 0; e < 4; e++){
            float a = bg[e];
            for (int ww = 0; ww < 16; ww++) a += sp[ww][e];
            lg[e] = a;
        }
        float m = fmaxf(fmaxf(lg[0],lg[1]), fmaxf(lg[2],lg[3]));
        float ex[4], se = 0.f;
        for (int e = 0; e < 4; e++){ ex[e] = expf(lg[e]-m); se += ex[e]; }
        for (int e = 0; e < 4; e++) g_raw[b*4+e] = ex[e]/se;
    }
}

// ---------------- K2: top-k, mask, denom, aux loss, gate scores ------------
__global__ void k_gatefin(){
    __shared__ float sraw[32][4];
    __shared__ float smask[32][4];
    __shared__ float sden[4];
    int b = threadIdx.x;  // 32 threads
    float r[4];
    #pragma unroll
    for (int e = 0; e < 4; e++){ r[e] = g_raw[b*4+e]; sraw[b][e] = r[e]; }
    int i0 = 0; float m0 = r[0];
    #pragma unroll
    for (int e = 1; e < 4; e++) if (r[e] > m0){ m0 = r[e]; i0 = e; }
    int i1 = -1; float m1 = -1e30f;
    #pragma unroll
    for (int e = 0; e < 4; e++) if (e != i0 && r[e] > m1){ m1 = r[e]; i1 = e; }
    #pragma unroll
    for (int e = 0; e < 4; e++) smask[b][e] = (e==i0 || e==i1) ? 1.f : 0.f;
    __syncthreads();
    if (b == 0){
        float aux = 0.f;
        for (int e = 0; e < 4; e++){
            float ds = 0.f, imp = 0.f, ld = 0.f;
            for (int bb = 0; bb < 32; bb++){
                ds  += sraw[bb][e]*smask[bb][e];
                imp += sraw[bb][e];
                ld  += smask[bb][e];
            }
            sden[e] = ds + 1e-6f;
            imp *= (1.f/32.f); ld *= (1.f/32.f);
            aux += (ld-imp)*(ld-imp);
        }
        g_aux = 0.01f * aux * 0.25f;
    }
    __syncthreads();
    const float cap = 40.f;   // int(1.25*32)
    float s0 = r[i0]*cap/sden[i0];
    float s1 = r[i1]*cap/sden[i1];
    int a0 = i0, a1 = i1; float v0 = s0, v1 = s1;
    if (v1 > v0 || (v1 == v0 && a1 < a0)){
        int t = a0; a0 = a1; a1 = t;
        float tv = v0; v0 = v1; v1 = tv;
    }
    g_topi[b*2] = a0; g_topi[b*2+1] = a1;
    g_topv[b*2] = v0; g_topv[b*2+1] = v1;
}

// ---------------- K3: in_proj GEMM + fused depthwise conv -> g_v -----------
// grid (64 slots, 2 roles) x 512 threads. sx TRANSPOSED in smem (stride 54).
// Thread tile 4 cols x (7|6) l-pairs; each xp LDS.64 feeds 4 FFMA2
// (crossbar halved vs 2-col). Register budget ~90 (no spills).
#define SXS 54
#define IP_SMEM ((DD*SXS + LL*DD)*4)   // 110592 + 100352 = 210944
template<int NP>
__device__ __forceinline__ void ip_phaseA(
    const float* __restrict__ sxT, float* __restrict__ sxin,
    const float* __restrict__ We, const float* __restrict__ bip,
    float* __restrict__ zout, int role, int lbase, int c0)
{
    unsigned long long acc[4][NP];
    #pragma unroll
    for (int c = 0; c < 4; c++)
        #pragma unroll
        for (int p = 0; p < NP; p++) acc[c][p] = 0ull;

    #pragma unroll 2
    for (int kk = 0; kk < DD; kk++){
        float4 w = *(const float4*)(We + (size_t)kk*C2);
        const float* xr = sxT + kk*SXS + lbase;
        unsigned long long xp[NP];
        #pragma unroll
        for (int p = 0; p < NP; p++)
            xp[p] = *(const unsigned long long*)(xr + 2*p);
        unsigned long long wd;
        wd = pk2(w.x, w.x);
        #pragma unroll
        for (int p = 0; p < NP; p++) fma2(acc[0][p], wd, xp[p]);
        wd = pk2(w.y, w.y);
        #pragma unroll
        for (int p = 0; p < NP; p++) fma2(acc[1][p], wd, xp[p]);
        wd = pk2(w.z, w.z);
        #pragma unroll
        for (int p = 0; p < NP; p++) fma2(acc[2][p], wd, xp[p]);
        wd = pk2(w.w, w.w);
        #pragma unroll
        for (int p = 0; p < NP; p++) fma2(acc[3][p], wd, xp[p]);
    }
    // epilogue: bias + store
    float4 bia = *(const float4*)(bip);
    float* dst = (role == 0) ? sxin : zout;
    #pragma unroll
    for (int p = 0; p < NP; p++){
        int l0 = lbase + 2*p, l1 = l0 + 1;
        float lo0, hi0, lo1, hi1, lo2, hi2, lo3, hi3;
        upk2(acc[0][p], lo0, hi0);
        upk2(acc[1][p], lo1, hi1);
        upk2(acc[2][p], lo2, hi2);
        upk2(acc[3][p], lo3, hi3);
        if (l0 < LL){
            *(float4*)(dst + (size_t)l0*DD + c0) =
                make_float4(lo0+bia.x, lo1+bia.y, lo2+bia.z, lo3+bia.w);
        }
        if (l1 < LL){
            *(float4*)(dst + (size_t)l1*DD + c0) =
                make_float4(hi0+bia.x, hi1+bia.y, hi2+bia.z, hi3+bia.w);
        }
    }
}

__global__ void __launch_bounds__(512, 1)
k_inproj(const float* __restrict__ x, const float* __restrict__ Wi,
         const float* __restrict__ bi, const float* __restrict__ cw,
         const float* __restrict__ cb){
    extern __shared__ float sm_[];
    float* sxT  = sm_;             // [DD][SXS]
    float* sxin = sm_ + DD*SXS;    // [LL][DD] (role 0 only)
    int s = blockIdx.x, role = blockIdx.y, tid = threadIdx.x;
    int b = s >> 1;
    int e = g_topi[s];
    const float* xb = x + (size_t)b*LL*DD;
    // load + transpose x
    for (int i = tid; i < LL*DD; i += 512){
        int l = i >> 9, d = i & 511;
        sxT[d*SXS + l] = xb[i];
    }
    {
        int d = tid;
        #pragma unroll
        for (int l = 49; l < SXS; l++) sxT[d*SXS + l] = 0.f;
    }
    __syncthreads();

    int cg = tid & 127, lg = tid >> 7;   // 128 cgroups x 4 lgroups
    int c0 = cg*4;
    const float* We  = Wi + (size_t)e*DD*C2 + role*DD + c0;
    const float* bip = bi + e*C2 + role*DD + c0;
    float* zout = g_z + (size_t)s*LL*DD;
    // pairs: lg0 -> 7 pairs (l 0..13), lg1/2/3 -> 6 pairs (l 14..49)
    if (lg == 0){
        ip_phaseA<7>(sxT, sxin, We, bip, zout, role, 0, c0);
    } else {
        ip_phaseA<6>(sxT, sxin, We, bip, zout, role, 14 + (lg-1)*12, c0);
    }
    if (role != 0) return;
    __syncthreads();
    // ---- depthwise 3x3 conv + silu -> g_v (single write); d = tid ----
    float* vout = g_v + (size_t)s*LL*DD;
    {
        int d = tid;
        float w9[9];
        #pragma unroll
        for (int t = 0; t < 9; t++) w9[t] = cw[(e*DD+d)*9 + t];
        float bias = cb[e*DD+d];
        float row[3][7];
        #pragma unroll
        for (int j = 0; j < 7; j++){
            row[0][j] = sxin[(0*7+j)*DD + d];
            row[1][j] = sxin[(1*7+j)*DD + d];
        }
        #pragma unroll
        for (int i = 0; i < 7; i++){
            if (i < 6){
                #pragma unroll
                for (int j = 0; j < 7; j++)
                    row[(i+1)%3][j] = sxin[((i+1)*7+j)*DD + d];
            }
            const float* rm = (i > 0) ? row[(i-1)%3] : nullptr;
            const float* rc = row[i%3];
            const float* rp = (i < 6) ? row[(i+1)%3] : nullptr;
            #pragma unroll
            for (int j = 0; j < 7; j++){
                float a = bias;
                #pragma unroll
                for (int dj = 0; dj < 3; dj++){
                    int jj = j + dj - 1;
                    if (jj < 0 || jj > 6) continue;
                    if (i > 0) a += rm[jj]*w9[0*3+dj];
                    a += rc[jj]*w9[1*3+dj];
                    if (i < 6) a += rp[jj]*w9[2*3+dj];
                }
                float v = a / (1.f + __expf(-a));   // silu
                vout[(i*7+j)*DD + d] = v;
            }
        }
    }
}

// ---------------- K5a: merged x_dbl GEMM (all 4 dirs) + dt_proj ------------
// grid (64 slots, 2 roles) x 512 threads. Thread tile 4 cols x (2|1) l-pairs.
#define SX2 54
#define XD_SMEM ((DD*SX2 + 128*SX2)*4)   // 110592 + 27648 = 138240
template<int NP>
__device__ __forceinline__ void xd_phaseA(
    const float* __restrict__ vT, float* __restrict__ sY,
    const float* __restrict__ Wp, int lbase, int cg)
{
    unsigned long long acc[4][NP];
    #pragma unroll
    for (int c = 0; c < 4; c++)
        #pragma unroll
        for (int p = 0; p < NP; p++) acc[c][p] = 0ull;
    #pragma unroll 2
    for (int kk = 0; kk < DD; kk++){
        float4 w = *(const float4*)(Wp + (size_t)kk*256);
        const float* xr = vT + kk*SX2 + lbase;
        unsigned long long xp[NP];
        #pragma unroll
        for (int p = 0; p < NP; p++)
            xp[p] = *(const unsigned long long*)(xr + 2*p);
        unsigned long long wd;
        wd = pk2(w.x, w.x);
        #pragma unroll
        for (int p = 0; p < NP; p++) fma2(acc[0][p], wd, xp[p]);
        wd = pk2(w.y, w.y);
        #pragma unroll
        for (int p = 0; p < NP; p++) fma2(acc[1][p], wd, xp[p]);
        wd = pk2(w.z, w.z);
        #pragma unroll
        for (int p = 0; p < NP; p++) fma2(acc[2][p], wd, xp[p]);
        wd = pk2(w.w, w.w);
        #pragma unroll
        for (int p = 0; p < NP; p++) fma2(acc[3][p], wd, xp[p]);
    }
    // epilogue -> sY
    #pragma unroll
    for (int c = 0; c < 4; c++){
        int rowi = cg*4 + c;
        #pragma unroll
        for (int p = 0; p < NP; p++){
            float lo, hi;
            upk2(acc[c][p], lo, hi);
            *(float2*)(sY + rowi*SX2 + lbase + 2*p) = make_float2(lo, hi);
        }
    }
}

__global__ void __launch_bounds__(512, 1)
k_xdbl(const float* __restrict__ dtb_){
    extern __shared__ float sm[];
    float* vT = sm;                  // [DD][SX2]
    float* sY = sm + DD*SX2;         // [128][SX2]  Y rows for this role
    int s = blockIdx.x, role = blockIdx.y, tid = threadIdx.x;
    int e = g_topi[s];

    // load + transpose v
    const float* vsrc = g_v + (size_t)s*LL*DD;
    for (int i = tid; i < LL*DD; i += 512){
        int l = i >> 9, d = i & 511;
        vT[d*SX2 + l] = vsrc[i];
    }
    {
        int d = tid;
        #pragma unroll
        for (int l = 49; l < SX2; l++) vT[d*SX2 + l] = 0.f;
    }
    __syncthreads();

    // ---- phase A: Y[kc][l] = sum_d v[l][d] * xpwT[e][d][kc] ----
    int cg = tid & 31, lg = tid >> 5;            // 32 cgroups x 16 lgroups
    int kc0 = role*128 + cg*4;
    const float* Wp = g_xpwT + (size_t)e*DD*256 + kc0;
    if (lg < 11){
        xd_phaseA<2>(vT, sY, Wp, lg*4, cg);
    } else {
        xd_phaseA<1>(vT, sY, Wp, 44 + (lg-11)*2, cg);
    }
    __syncthreads();

    // ---- write B/C for this role's 2 directions ----
    for (int i = tid; i < 2*LL*NS; i += 512){
        int kloc = i / (LL*NS);
        int rem  = i - kloc*LL*NS;
        int l = rem >> 4, n = rem & 15;
        int k = role*2 + kloc;
        g_Bm[((size_t)(s*KDn + k)*LL + l)*NS + n] = sY[(kloc*64 + 32 + n)*SX2 + l];
        g_Cm[((size_t)(s*KDn + k)*LL + l)*NS + n] = sY[(kloc*64 + 48 + n)*SX2 + l];
    }

    // ---- dt_proj + softplus for the role's 2 directions; thread = dd ----
    int dd = tid;
    const float L2E = 1.44269504088896f;
    const float LN2 = 0.69314718055995f;
    #pragma unroll 1
    for (int kloc = 0; kloc < 2; kloc++){
        int k = role*2 + kloc;
        float bias = dtb_[(e*KDn + k)*DD + dd];
        // coalesced transposed dtw loads
        float wreg[32];
        {
            const float* wt = g_dtwT + (size_t)(e*KDn + k)*DD*RR + dd;
            #pragma unroll
            for (int r = 0; r < RR; r++) wreg[r] = wt[(size_t)r*DD];
        }
        unsigned long long acc[26];
        unsigned long long binit = pk2(bias, bias);
        #pragma unroll
        for (int t = 0; t < 26; t++) acc[t] = binit;
        const float* sb = sY + (kloc*64)*SX2;
        #pragma unroll 4
        for (int r = 0; r < RR; r++){
            unsigned long long wd = pk2(wreg[r], wreg[r]);
            const float* srow = sb + r*SX2;
            #pragma unroll
            for (int t = 0; t < 26; t++){
                unsigned long long xp = *(const unsigned long long*)(srow + 2*t);
                fma2(acc[t], wd, xp);
            }
        }
        float* dtout = g_dt + (size_t)(s*KDn + k)*LL*DD + dd;
        #pragma unroll
        for (int t = 0; t < 26; t++){
            float a_lo, a_hi;
            upk2(acc[t], a_lo, a_hi);
            int l0 = 2*t, l1 = 2*t + 1;
            if (l0 < LL){
                float dtv = fmaxf(a_lo, 0.f) + LN2*lg2f(1.f + ex2f(-fabsf(a_lo)*L2E));
                dtout[l0*DD] = dtv;
            }
            if (l1 < LL){
                float dtv = fmaxf(a_hi, 0.f) + LN2*lg2f(1.f + ex2f(-fabsf(a_hi)*L2E));
                dtout[l1*DD] = dtv;
            }
        }
    }
}

// ---------------- K5b: selective scan (v-space, permuted indexing) ---------
// grid = 256 blocks (s,k), 512 threads, thread = channel dd.
__global__ void __launch_bounds__(512, 2)
k_scan(const float* __restrict__ alog_, const float* __restrict__ ds_){
    __shared__ float sB[LL*NS];
    __shared__ float sC[LL*NS];
    __shared__ int   sPerm[LL];
    int idx = blockIdx.x;
    int k = idx & 3, s = idx >> 2;
    int e = g_topi[s];
    int dd = threadIdx.x;
    size_t skbase = (size_t)(s*KDn + k);
    {
        const float* Bg = g_Bm + skbase*LL*NS;
        const float* Cg = g_Cm + skbase*LL*NS;
        for (int i = dd; i < LL*NS; i += 512){ sB[i] = Bg[i]; sC[i] = Cg[i]; }
    }
    if (dd < LL){
        int t = dd;
        int tt = (k & 1) ? (48 - t) : t;
        int lsrc = (k >= 2) ? ((tt % 7)*7 + tt/7) : tt;
        sPerm[t] = lsrc;
    }
    float A[NS];
    {
        const float4* al = (const float4*)(alog_ + ((size_t)((e*KDn+k)*DD) + dd)*NS);
        const float L2E = 1.44269504088896f;
        #pragma unroll
        for (int q = 0; q < 4; q++){
            float4 v = al[q];
            A[q*4+0] = -__expf(v.x)*L2E; A[q*4+1] = -__expf(v.y)*L2E;
            A[q*4+2] = -__expf(v.z)*L2E; A[q*4+3] = -__expf(v.w)*L2E;
        }
    }
    float Dd = ds_[(e*KDn+k)*DD + dd];
    const float* dtp = g_dt + skbase*LL*DD + dd;
    const float* vp  = g_v  + (size_t)s*LL*DD + dd;
    float*       ysp = g_ys + skbase*LL*DD + dd;
    __syncthreads();
    float h[NS];
    #pragma unroll
    for (int n = 0; n < NS; n++) h[n] = 0.f;
    int lcur = sPerm[0];
    float dtc = dtp[lcur*DD], xvc = vp[lcur*DD];
    #pragma unroll 1
    for (int t = 0; t < LL; t++){
        int lnext = (t < LL-1) ? sPerm[t+1] : 0;
        float dtn = 0.f, xvn = 0.f;
        if (t < LL-1){ dtn = dtp[lnext*DD]; xvn = vp[lnext*DD]; }
        float dx = dtc*xvc;
        const float* Bl = sB + lcur*NS;
        const float* Cl = sC + lcur*NS;
        float y = 0.f;
        #pragma unroll
        for (int n = 0; n < NS; n++){
            h[n] = h[n]*ex2f(dtc*A[n]) + dx*Bl[n];
            y += h[n]*Cl[n];
        }
        ysp[lcur*DD] = y + Dd*xvc;
        lcur = lnext; dtc = dtn; xvc = xvn;
    }
}

// ---------------- block reduction (sum, sumsq) over 512 threads ------------
__device__ __forceinline__ float2 blockReduce2(float a, float b){
    __shared__ float sa[16], sb[16];
    __shared__ float2 res;
    int lane = threadIdx.x & 31, w = threadIdx.x >> 5;
    #pragma unroll
    for (int o = 16; o; o >>= 1){
        a += __shfl_xor_sync(0xffffffffu, a, o);
        b += __shfl_xor_sync(0xffffffffu, b, o);
    }
    __syncthreads();
    if (lane == 0){ sa[w] = a; sb[w] = b; }
    __syncthreads();
    if (w == 0){
        a = (lane < 16) ? sa[lane] : 0.f;
        b = (lane < 16) ? sb[lane] : 0.f;
        #pragma unroll
        for (int o = 8; o; o >>= 1){
            a += __shfl_xor_sync(0xffffffffu, a, o);
            b += __shfl_xor_sync(0xffffffffu, b, o);
        }
        if (lane == 0){ res.x = a; res.y = b; }
    }
    __syncthreads();
    return res;
}

// ---------------- K7: combine directions + LN + silu(z) gate + pool + LN ---
#define CB_SMEM ((LL*DD + 128)*4)
__global__ void __launch_bounds__(512, 1)
k_combine(const float* __restrict__ og_, const float* __restrict__ ob_,
          const float* __restrict__ ng_, const float* __restrict__ nb_){
    extern __shared__ float sv[];        // 49*512 + mu/rs
    float* smu = sv + LL*DD;             // 49
    float* srs = smu + 56;               // 49
    int s = blockIdx.x, d = threadIdx.x;   // 64 slots, 512 threads
    int e = g_topi[s];
    const float* y0 = g_ys + (size_t)(s*KDn + 0)*LL*DD;
    const float* y1 = g_ys + (size_t)(s*KDn + 1)*LL*DD;
    const float* y2 = g_ys + (size_t)(s*KDn + 2)*LL*DD;
    const float* y3 = g_ys + (size_t)(s*KDn + 3)*LL*DD;
    #pragma unroll 2
    for (int l = 0; l < LL; l++){
        int o = l*DD + d;
        sv[o] = y0[o] + y1[o] + y2[o] + y3[o];
    }
    __syncthreads();
    int w = d >> 5, lane = d & 31;
    for (int l = w; l < LL; l += 16){
        float a = 0.f, s2 = 0.f;
        #pragma unroll
        for (int jj = 0; jj < 16; jj++){
            float xv = sv[l*DD + lane + 32*jj];
            a += xv; s2 += xv*xv;
        }
        #pragma unroll
        for (int o = 16; o; o >>= 1){
            a  += __shfl_xor_sync(0xffffffffu, a, o);
            s2 += __shfl_xor_sync(0xffffffffu, s2, o);
        }
        if (lane == 0){
            float mu = a*(1.f/512.f);
            float var = s2*(1.f/512.f) - mu*mu;
            smu[l] = mu;
            srs[l] = rsqrtf(var + 1e-5f);
        }
    }
    __syncthreads();
    float og = og_[e*DD+d], ob = ob_[e*DD+d];
    const float* zrow = g_z + (size_t)s*LL*DD + d;
    float pooled = 0.f;
    #pragma unroll 7
    for (int l = 0; l < LL; l++){
        float v = sv[l*DD + d];
        float yn = (v - smu[l])*srs[l]*og + ob;
        float z = zrow[l*DD];
        pooled += yn * (z / (1.f + __expf(-z)));
    }
    pooled *= (1.f/49.f);
    float2 ss = blockReduce2(pooled, pooled*pooled);
    float mu = ss.x*(1.f/512.f);
    float var = ss.y*(1.f/512.f) - mu*mu;
    float rs = rsqrtf(var + 1e-5f);
    g_allout[s*DD + d] = (pooled - mu)*rs*ng_[e*DD+d] + nb_[e*DD+d];
}

// ---------------- K8: mixture + aux loss output -----------------------------
__global__ void k_mix(float* __restrict__ out, int out_size){
    int b = blockIdx.x, d = threadIdx.x;
    float v0 = g_topv[b*2], v1 = g_topv[b*2+1];
    out[b*DD + d] = v0*g_allout[(b*2)*DD + d] + v1*g_allout[(b*2+1)*DD + d];
    if (b == 0 && d == 0 && out_size > BB*DD) out[BB*DD] = g_aux;
}

// ---------------- launch ----------------------------------------------------
extern "C" void kernel_launch(void* const* d_in, const int* in_sizes, int n_in,
                              void* d_out, int out_size){
    const float* x    = (const float*)d_in[0];
    const float* wg   = (const float*)d_in[1];
    const float* bg   = (const float*)d_in[2];
    const float* ipw  = (const float*)d_in[3];
    const float* ipb  = (const float*)d_in[4];
    const float* cw   = (const float*)d_in[5];
    const float* cb   = (const float*)d_in[6];
    const float* xpw  = (const float*)d_in[7];
    const float* dtw  = (const float*)d_in[8];
    const float* dtb  = (const float*)d_in[9];
    const float* alog = (const float*)d_in[10];
    const float* ds   = (const float*)d_in[11];
    const float* ong  = (const float*)d_in[12];
    const float* onb  = (const float*)d_in[13];
    const float* ng   = (const float*)d_in[14];
    const float* nb   = (const float*)d_in[15];
    float* out = (float*)d_out;

    cudaFuncSetAttribute(k_inproj,  cudaFuncAttributeMaxDynamicSharedMemorySize, IP_SMEM);
    cudaFuncSetAttribute(k_xdbl,    cudaFuncAttributeMaxDynamicSharedMemorySize, XD_SMEM);
    cudaFuncSetAttribute(k_combine, cudaFuncAttributeMaxDynamicSharedMemorySize, CB_SMEM);

    k_wt      <<<EE*KDn*64, 128>>>(xpw);
    k_wt2     <<<EE*KDn, 512>>>(dtw);
    k_gate    <<<32, 512>>>(x, wg, bg);
    k_gatefin <<<1, 32>>>();
    k_inproj  <<<dim3(NSLOT, 2), 512, IP_SMEM>>>(x, ipw, ipb, cw, cb);
    k_xdbl    <<<dim3(NSLOT, 2), 512, XD_SMEM>>>(dtb);
    k_scan    <<<NSLOT*KDn, 512>>>(alog, ds);
    k_combine <<<NSLOT, 512, CB_SMEM>>>(ong, onb, ng, nb);
    k_mix     <<<BB, 512>>>(out, out_size);
}

// round 13
// speedup vs baseline: 1.7353x; 1.5132x over previous
#include <cuda_runtime.h>
#include <math.h>

// Problem constants
#define EE  4      // experts
#define BB  32     // batch
#define HH  7
#define LL  49     // H*W
#define DD  512    // dim
#define C2  1024   // 2*dim
#define RR  32     // DT_RANK
#define NS  16     // N_STATE
#define KDn 4      // directions
#define NSLOT (BB*2)   // 64 selected (b, expert) slots

// ---------------- scratch (device globals; no allocation allowed) ----------
__device__ float g_z [EE*BB*LL*DD];          // z half of in_proj [e][b][l][d]
__device__ float g_xs[EE*BB*KDn*LL*DD];      // 4-direction scan inputs
__device__ float g_ys[EE*BB*KDn*LL*DD];      // scan outputs
__device__ float g_dt[NSLOT*KDn*LL*DD];      // softplus(dt), slot-indexed
__device__ float g_Bm[NSLOT*KDn*LL*NS];      // B, slot-indexed
__device__ float g_Cm[NSLOT*KDn*LL*NS];      // C, slot-indexed
__device__ float g_poolp[4*NSLOT*DD];        // partial pooled sums per l-chunk
__device__ float g_raw[BB*EE];
__device__ float g_aux;
__device__ int   g_ctr;                      // last-block-done counter (self-reset)
__device__ int   g_topi[NSLOT];              // slot s -> expert  (b = s>>1)
__device__ float g_topv[NSLOT];              // slot s -> gate coeff

// ---------------- f32x2 packed FMA helpers (sm_103a) -----------------------
__device__ __forceinline__ unsigned long long pk2(float lo, float hi){
    unsigned long long r;
    asm("mov.b64 %0, {%1, %2};" : "=l"(r) : "f"(lo), "f"(hi));
    return r;
}
__device__ __forceinline__ void fma2(unsigned long long& d, unsigned long long a, unsigned long long b){
    asm("fma.rn.f32x2 %0, %1, %2, %0;" : "+l"(d) : "l"(a), "l"(b));
}
__device__ __forceinline__ void upk2(unsigned long long v, float& lo, float& hi){
    asm("mov.b64 {%0, %1}, %2;" : "=f"(lo), "=f"(hi) : "l"(v));
}
__device__ __forceinline__ float ex2f(float x){
    float r; asm("ex2.approx.f32 %0, %1;" : "=f"(r) : "f"(x)); return r;
}
__device__ __forceinline__ float lg2f(float x){
    float r; asm("lg2.approx.f32 %0, %1;" : "=f"(r) : "f"(x)); return r;
}

// ---------------- K1: gate softmax + fused top-k/aux (last block) ----------
__global__ void k_gate(const float* __restrict__ x, const float* __restrict__ wg,
                       const float* __restrict__ bg){
    int b = blockIdx.x, tid = threadIdx.x;           // 512 threads, tid = channel
    const float* xb = x + (size_t)b*LL*DD + tid;
    float s = 0.f;
    #pragma unroll 7
    for (int l = 0; l < LL; l++) s += xb[l*DD];
    s *= (1.f/49.f);
    float p0 = s*wg[tid*EE+0], p1 = s*wg[tid*EE+1];
    float p2 = s*wg[tid*EE+2], p3 = s*wg[tid*EE+3];
    #pragma unroll
    for (int o = 16; o; o >>= 1){
        p0 += __shfl_xor_sync(0xffffffffu, p0, o);
        p1 += __shfl_xor_sync(0xffffffffu, p1, o);
        p2 += __shfl_xor_sync(0xffffffffu, p2, o);
        p3 += __shfl_xor_sync(0xffffffffu, p3, o);
    }
    __shared__ float sp[16][4];
    int w = tid >> 5, lane = tid & 31;
    if (lane == 0){ sp[w][0]=p0; sp[w][1]=p1; sp[w][2]=p2; sp[w][3]=p3; }
    __syncthreads();
    if (tid == 0){
        float lg[4];
        for (int e = 0; e < 4; e++){
            float a = bg[e];
            for (int ww = 0; ww < 16; ww++) a += sp[ww][e];
            lg[e] = a;
        }
        float m = fmaxf(fmaxf(lg[0],lg[1]), fmaxf(lg[2],lg[3]));
        float ex[4], se = 0.f;
        for (int e = 0; e < 4; e++){ ex[e] = expf(lg[e]-m); se += ex[e]; }
        for (int e = 0; e < 4; e++) g_raw[b*4+e] = ex[e]/se;
    }
    // ---- last-block-done: run the gate finalization in whichever block
    // finishes last (deterministic result; counter self-resets) ----
    __shared__ int sdone;
    if (tid == 0){
        __threadfence();
        int old = atomicAdd(&g_ctr, 1);
        sdone = (old == BB-1) ? 1 : 0;
    }
    __syncthreads();
    if (sdone){
        __threadfence();
        __shared__ float sraw[32][4];
        __shared__ float smask[32][4];
        __shared__ float sden[4];
        if (tid < 32){
            int bb = tid;
            float r[4];
            #pragma unroll
            for (int e = 0; e < 4; e++){ r[e] = g_raw[bb*4+e]; sraw[bb][e] = r[e]; }
            int i0 = 0; float m0 = r[0];
            #pragma unroll
            for (int e = 1; e < 4; e++) if (r[e] > m0){ m0 = r[e]; i0 = e; }
            int i1 = -1; float m1 = -1e30f;
            #pragma unroll
            for (int e = 0; e < 4; e++) if (e != i0 && r[e] > m1){ m1 = r[e]; i1 = e; }
            #pragma unroll
            for (int e = 0; e < 4; e++) smask[bb][e] = (e==i0 || e==i1) ? 1.f : 0.f;
        }
        __syncthreads();
        if (tid == 0){
            float aux = 0.f;
            for (int e = 0; e < 4; e++){
                float ds = 0.f, imp = 0.f, ld = 0.f;
                for (int bb = 0; bb < 32; bb++){
                    ds  += sraw[bb][e]*smask[bb][e];
                    imp += sraw[bb][e];
                    ld  += smask[bb][e];
                }
                sden[e] = ds + 1e-6f;
                imp *= (1.f/32.f); ld *= (1.f/32.f);
                aux += (ld-imp)*(ld-imp);
            }
            g_aux = 0.01f * aux * 0.25f;
        }
        __syncthreads();
        if (tid < 32){
            int bb = tid;
            float r[4];
            #pragma unroll
            for (int e = 0; e < 4; e++) r[e] = sraw[bb][e];
            int i0 = 0; float m0 = r[0];
            #pragma unroll
            for (int e = 1; e < 4; e++) if (r[e] > m0){ m0 = r[e]; i0 = e; }
            int i1 = -1; float m1 = -1e30f;
            #pragma unroll
            for (int e = 0; e < 4; e++) if (e != i0 && r[e] > m1){ m1 = r[e]; i1 = e; }
            const float cap = 40.f;   // int(1.25*32)
            float s0 = r[i0]*cap/sden[i0];
            float s1 = r[i1]*cap/sden[i1];
            int a0 = i0, a1 = i1; float v0 = s0, v1 = s1;
            if (v1 > v0 || (v1 == v0 && a1 < a0)){
                int t = a0; a0 = a1; a1 = t;
                float tv = v0; v0 = v1; v1 = tv;
            }
            g_topi[bb*2] = a0; g_topi[bb*2+1] = a1;
            g_topv[bb*2] = v0; g_topv[bb*2+1] = v1;
        }
        __syncthreads();
        if (tid == 0) g_ctr = 0;   // reset for next graph replay
    }
}

// ---------------- K3: in_proj GEMM + fused depthwise conv + scatter --------
// grid (64 slots, 2 roles) x 512 threads. sx stored TRANSPOSED in smem
// (sxT[d][l], stride 52). Thread: cth = tid&255 owns 2 cols; lg = tid>>8
// owns l-pairs [lg*26, +26). Role 0 -> xin (smem) + conv; role 1 -> z.
#define SXS 52
#define IP_SMEM ((DD*SXS + LL*DD)*4)   // 106496 + 100352 = 206848
__global__ void __launch_bounds__(512, 1)
k_inproj(const float* __restrict__ x, const float* __restrict__ Wi,
         const float* __restrict__ bi, const float* __restrict__ cw,
         const float* __restrict__ cb){
    extern __shared__ float sm_[];
    float* sxT  = sm_;             // [DD][SXS]
    float* sxin = sm_ + DD*SXS;    // [LL][DD] (role 0 only)
    int s = blockIdx.x, role = blockIdx.y, tid = threadIdx.x;
    int b = s >> 1;
    int e = g_topi[s];
    const float* xb = x + (size_t)b*LL*DD;
    // load + transpose x
    for (int i = tid; i < LL*DD; i += 512){
        int l = i >> 9, d = i & 511;
        sxT[d*SXS + l] = xb[i];
    }
    {
        int d = tid;
        sxT[d*SXS + 49] = 0.f; sxT[d*SXS + 50] = 0.f; sxT[d*SXS + 51] = 0.f;
    }
    __syncthreads();

    int cth = tid & 255, lg = tid >> 8;
    int c0 = cth*2;                      // local col within role's 512
    int lbase = lg*26;
    const float* We = Wi + (size_t)e*DD*C2 + role*DD + c0;
    float2 bia = *(const float2*)(bi + e*C2 + role*DD + c0);
    float* zout = g_z + (size_t)(e*BB+b)*LL*DD;

    unsigned long long acc0[13], acc1[13];
    #pragma unroll
    for (int p = 0; p < 13; p++){ acc0[p] = 0ull; acc1[p] = 0ull; }

    #pragma unroll 4
    for (int kk = 0; kk < DD; kk++){
        float2 w = *(const float2*)(We + (size_t)kk*C2);
        unsigned long long w0 = pk2(w.x, w.x);
        unsigned long long w1 = pk2(w.y, w.y);
        const float* xr = sxT + kk*SXS + lbase;
        #pragma unroll
        for (int p = 0; p < 13; p++){
            unsigned long long xp = *(const unsigned long long*)(xr + 2*p);
            fma2(acc0[p], w0, xp);
            fma2(acc1[p], w1, xp);
        }
    }

    // epilogue: add bias, store (role 0 -> sxin smem, role 1 -> g_z)
    #pragma unroll
    for (int p = 0; p < 13; p++){
        int l0 = lbase + 2*p, l1 = l0 + 1;
        float a00, a01, a10, a11;
        upk2(acc0[p], a00, a01);   // (c0 @ l0, c0 @ l1)
        upk2(acc1[p], a10, a11);   // (c1 @ l0, c1 @ l1)
        if (l0 < LL){
            float2 o = make_float2(a00 + bia.x, a10 + bia.y);
            if (role == 0) *(float2*)(sxin + (size_t)l0*DD + c0) = o;
            else           *(float2*)(zout + (size_t)l0*DD + c0) = o;
        }
        if (l1 < LL){
            float2 o = make_float2(a01 + bia.x, a11 + bia.y);
            if (role == 0) *(float2*)(sxin + (size_t)l1*DD + c0) = o;
            else           *(float2*)(zout + (size_t)l1*DD + c0) = o;
        }
    }
    if (role != 0) return;
    __syncthreads();
    // ---- depthwise 3x3 conv + silu + 4-direction scatter; d = tid ----
    float* xsb = g_xs + (size_t)(e*BB+b)*KDn*LL*DD;
    {
        int d = tid;
        float w9[9];
        #pragma unroll
        for (int t = 0; t < 9; t++) w9[t] = cw[(e*DD+d)*9 + t];
        float bias = cb[e*DD+d];
        float row[3][7];
        #pragma unroll
        for (int j = 0; j < 7; j++){
            row[0][j] = sxin[(0*7+j)*DD + d];
            row[1][j] = sxin[(1*7+j)*DD + d];
        }
        #pragma unroll
        for (int i = 0; i < 7; i++){
            if (i < 6){
                #pragma unroll
                for (int j = 0; j < 7; j++)
                    row[(i+1)%3][j] = sxin[((i+1)*7+j)*DD + d];
            }
            const float* rm = (i > 0) ? row[(i-1)%3] : nullptr;
            const float* rc = row[i%3];
            const float* rp = (i < 6) ? row[(i+1)%3] : nullptr;
            #pragma unroll
            for (int j = 0; j < 7; j++){
                float a = bias;
                #pragma unroll
                for (int dj = 0; dj < 3; dj++){
                    int jj = j + dj - 1;
                    if (jj < 0 || jj > 6) continue;
                    if (i > 0) a += rm[jj]*w9[0*3+dj];
                    a += rc[jj]*w9[1*3+dj];
                    if (i < 6) a += rp[jj]*w9[2*3+dj];
                }
                float v = a / (1.f + __expf(-a));   // silu
                int l  = i*7 + j;
                int lv = j*7 + i;
                xsb[(0*LL + l       )*DD + d] = v;
                xsb[(1*LL + (48-l)  )*DD + d] = v;
                xsb[(2*LL + lv      )*DD + d] = v;
                xsb[(3*LL + (48-lv) )*DD + d] = v;
            }
        }
    }
}

// ---------------- K5a: x_dbl GEMM + dt_proj GEMM + softplus ----------------
// grid = 64 slots x 4 k = 256 blocks, 512 threads. Writes g_dt (softplus'd),
// g_Bm, g_Cm.
#define DTW_S 513
#define XD_SMEM_BYTES ((LL*DD + 64*DD)*4)   // 100352 + 131072 = 231424
__global__ void __launch_bounds__(512, 1)
k_xdbl(const float* __restrict__ xpw_, const float* __restrict__ dtw_,
       const float* __restrict__ dtb_){
    extern __shared__ float sm[];
    float* sx  = sm;                 // LL*DD floats
    float* wsm = sm + LL*DD;         // 64 x 512, XOR-swizzled (phase A)
    float* dtwT = sm + LL*DD;        // 32 x DTW_S (phase B) aliases wsm
    float* sdbl = dtwT + 32*DTW_S;   // 49 x 32 dt-rank
    float* sBC  = sdbl + LL*32;      // 49 x 32 (B | C)
    int idx = blockIdx.x;
    int k = idx & 3, s = idx >> 2;
    int b = s >> 1;
    int e = g_topi[s];
    int tid = threadIdx.x;
    int lane = tid & 31, w = tid >> 5;

    const float* xsrow = g_xs + (size_t)((e*BB+b)*KDn + k)*LL*DD;
    const float* xpw = xpw_ + (size_t)((e*KDn+k)*64)*DD;   // [c][d]
    const float* dtw = dtw_ + (size_t)((e*KDn+k)*DD)*RR;   // [d][r]
    const float* dtb = dtb_ + (e*KDn+k)*DD;
    size_t skbase = (size_t)(s*KDn + k);
    float* dtout = g_dt + skbase*LL*DD;
    float* Bout  = g_Bm + skbase*LL*NS;
    float* Cout  = g_Cm + skbase*LL*NS;

    // load sx tile (coalesced) + xpw into XOR-swizzled smem
    for (int i = tid; i < LL*DD; i += 512) sx[i] = xsrow[i];
    for (int i = tid; i < 64*DD; i += 512){
        int c = i >> 9, dd = i & 511;
        int g = dd >> 2;
        wsm[c*DD + ((((g ^ (c & 7)) << 2)) | (dd & 3))] = xpw[i];
    }
    __syncthreads();

    // ---- Phase A: x_dbl[c][l] = sum_d sx[l][d]*w[c][d], split-K ----
    int wg = w & 7;            // l-group: wg*6..wg*6+5 (wg==0 also handles l=48)
    int ks = w >> 3;           // K-split half
    int kk0 = ks << 8;
    int l0 = wg*6;
    int nl = (wg == 0) ? 7 : 6;
    int c0 = lane, c1 = lane + 32;
    unsigned long long a0[7], a1[7];
    #pragma unroll
    for (int j = 0; j < 7; j++){ a0[j] = 0ull; a1[j] = 0ull; }
    const float* w0base = wsm + c0*DD;
    const float* w1base = wsm + c1*DD;
    int sw = (lane & 7) << 2;     // xor pattern
    #pragma unroll 4
    for (int t = 0; t < 64; t++){
        int kk = kk0 + t*4;
        float4 w0 = *(const float4*)(w0base + (kk ^ sw));
        float4 w1 = *(const float4*)(w1base + (kk ^ sw));
        unsigned long long w0a = pk2(w0.x, w0.y), w0b = pk2(w0.z, w0.w);
        unsigned long long w1a = pk2(w1.x, w1.y), w1b = pk2(w1.z, w1.w);
        #pragma unroll
        for (int j = 0; j < 7; j++){
            if (j < nl){
                int l = (j == 6) ? 48 : (l0 + j);
                float4 xv = *(const float4*)(sx + l*DD + kk);
                unsigned long long xa = pk2(xv.x, xv.y), xb = pk2(xv.z, xv.w);
                fma2(a0[j], w0a, xa); fma2(a0[j], w0b, xb);
                fma2(a1[j], w1a, xa); fma2(a1[j], w1b, xb);
            }
        }
    }
    __syncthreads();   // all wsm/sx phase-A reads done; wsm region reusable

    // stage: split-K half 0 writes, half 1 adds
    if (ks == 0){
        #pragma unroll
        for (int j = 0; j < 7; j++){
            if (j < nl){
                int l = (j == 6) ? 48 : (l0 + j);
                float lo, hi;
                upk2(a0[j], lo, hi); sdbl[l*32 + lane] = lo + hi;
                upk2(a1[j], lo, hi); sBC [l*32 + lane] = lo + hi;
            }
        }
    }
    __syncthreads();
    if (ks == 1){
        #pragma unroll
        for (int j = 0; j < 7; j++){
            if (j < nl){
                int l = (j == 6) ? 48 : (l0 + j);
                float lo, hi;
                upk2(a0[j], lo, hi); sdbl[l*32 + lane] += lo + hi;
                upk2(a1[j], lo, hi); sBC [l*32 + lane] += lo + hi;
            }
        }
    }
    // load dtw transposed into dtwT (disjoint from sdbl/sBC)
    for (int i = tid; i < DD*RR; i += 512){
        int dd = i >> 5, r = i & 31;
        dtwT[r*DTW_S + dd] = dtw[i];
    }
    __syncthreads();

    // write B/C to global
    for (int i = tid; i < LL*NS; i += 512){
        int l = i >> 4, n = i & 15;
        Bout[i] = sBC[l*32 + n];
        Cout[i] = sBC[l*32 + 16 + n];
    }

    // ---- dt projection + softplus; thread dd = tid ----
    int dd = tid;
    float bias = dtb[dd];
    const float L2E = 1.44269504088896f;
    const float LN2 = 0.69314718055995f;
    #pragma unroll 1
    for (int lg = 0; lg < 13; lg++){
        int l0b = lg*4;
        int nlb = (lg < 12) ? 4 : 1;
        float q0 = bias, q1 = bias, q2 = bias, q3 = bias;
        const float4* s0 = (const float4*)(sdbl + (l0b    )*32);
        const float4* s1 = (const float4*)(sdbl + (l0b + 1)*32);
        const float4* s2 = (const float4*)(sdbl + (l0b + 2)*32);
        const float4* s3 = (const float4*)(sdbl + (l0b + 3)*32);
        if (nlb == 4){
            #pragma unroll
            for (int rc = 0; rc < 8; rc++){
                float w0 = dtwT[(4*rc+0)*DTW_S + dd];
                float w1 = dtwT[(4*rc+1)*DTW_S + dd];
                float w2 = dtwT[(4*rc+2)*DTW_S + dd];
                float w3 = dtwT[(4*rc+3)*DTW_S + dd];
                float4 v0 = s0[rc], v1 = s1[rc], v2 = s2[rc], v3 = s3[rc];
                q0 += v0.x*w0 + v0.y*w1 + v0.z*w2 + v0.w*w3;
                q1 += v1.x*w0 + v1.y*w1 + v1.z*w2 + v1.w*w3;
                q2 += v2.x*w0 + v2.y*w1 + v2.z*w2 + v2.w*w3;
                q3 += v3.x*w0 + v3.y*w1 + v3.z*w2 + v3.w*w3;
            }
        } else {
            #pragma unroll
            for (int rc = 0; rc < 8; rc++){
                float w0 = dtwT[(4*rc+0)*DTW_S + dd];
                float w1 = dtwT[(4*rc+1)*DTW_S + dd];
                float w2 = dtwT[(4*rc+2)*DTW_S + dd];
                float w3 = dtwT[(4*rc+3)*DTW_S + dd];
                float4 v0 = s0[rc];
                q0 += v0.x*w0 + v0.y*w1 + v0.z*w2 + v0.w*w3;
            }
        }
        float dts[4] = {q0, q1, q2, q3};
        #pragma unroll
        for (int j = 0; j < 4; j++){
            if (j >= nlb) break;
            float a = dts[j];
            float dtv = fmaxf(a, 0.f) + LN2*lg2f(1.f + ex2f(-fabsf(a)*L2E));
            dtout[(l0b + j)*DD + dd] = dtv;
        }
    }
}

// ---------------- K5b: selective scan (lean; 2 blocks/SM) ------------------
// grid = 256 blocks (s,k), 512 threads, thread = channel dd.
__global__ void __launch_bounds__(512, 2)
k_scan(const float* __restrict__ alog_, const float* __restrict__ ds_){
    __shared__ float sB[LL*NS];
    __shared__ float sC[LL*NS];
    int idx = blockIdx.x;
    int k = idx & 3, s = idx >> 2;
    int b = s >> 1;
    int e = g_topi[s];
    int dd = threadIdx.x;
    size_t skbase = (size_t)(s*KDn + k);
    {
        const float* Bg = g_Bm + skbase*LL*NS;
        const float* Cg = g_Cm + skbase*LL*NS;
        for (int i = dd; i < LL*NS; i += 512){ sB[i] = Bg[i]; sC[i] = Cg[i]; }
    }
    float A[NS];
    {
        const float4* al = (const float4*)(alog_ + ((size_t)((e*KDn+k)*DD) + dd)*NS);
        const float L2E = 1.44269504088896f;
        #pragma unroll
        for (int q = 0; q < 4; q++){
            float4 v = al[q];
            A[q*4+0] = -__expf(v.x)*L2E; A[q*4+1] = -__expf(v.y)*L2E;
            A[q*4+2] = -__expf(v.z)*L2E; A[q*4+3] = -__expf(v.w)*L2E;
        }
    }
    float Dd = ds_[(e*KDn+k)*DD + dd];
    const float* dtp = g_dt + skbase*LL*DD + dd;
    const float* xsp = g_xs + (size_t)((e*BB+b)*KDn + k)*LL*DD + dd;
    float*       ysp = g_ys + (size_t)((e*BB+b)*KDn + k)*LL*DD + dd;
    __syncthreads();
    float h[NS];
    #pragma unroll
    for (int n = 0; n < NS; n++) h[n] = 0.f;
    float dtc = dtp[0], xvc = xsp[0];
    #pragma unroll 1
    for (int l = 0; l < LL; l++){
        float dtn = 0.f, xvn = 0.f;
        if (l < LL-1){ dtn = dtp[(l+1)*DD]; xvn = xsp[(l+1)*DD]; }
        float dx = dtc*xvc;
        const float* Bl = sB + l*NS;
        const float* Cl = sC + l*NS;
        float y = 0.f;
        #pragma unroll
        for (int n = 0; n < NS; n++){
            h[n] = h[n]*ex2f(dtc*A[n]) + dx*Bl[n];
            y += h[n]*Cl[n];
        }
        ysp[l*DD] = y + Dd*xvc;
        dtc = dtn; xvc = xvn;
    }
}

// ---------------- block reduction (sum, sumsq) over 512 threads ------------
__device__ __forceinline__ float2 blockReduce2(float a, float b){
    __shared__ float sa[16], sb[16];
    __shared__ float2 res;
    int lane = threadIdx.x & 31, w = threadIdx.x >> 5;
    #pragma unroll
    for (int o = 16; o; o >>= 1){
        a += __shfl_xor_sync(0xffffffffu, a, o);
        b += __shfl_xor_sync(0xffffffffu, b, o);
    }
    __syncthreads();
    if (lane == 0){ sa[w] = a; sb[w] = b; }
    __syncthreads();
    if (w == 0){
        a = (lane < 16) ? sa[lane] : 0.f;
        b = (lane < 16) ? sb[lane] : 0.f;
        #pragma unroll
        for (int o = 8; o; o >>= 1){
            a += __shfl_xor_sync(0xffffffffu, a, o);
            b += __shfl_xor_sync(0xffffffffu, b, o);
        }
        if (lane == 0){ res.x = a; res.y = b; }
    }
    __syncthreads();
    return res;
}

// ---------------- K7: combine dirs + LN + silu(z) gate, CHUNKED over l -----
// grid (64 slots, 4 chunks) x 512 threads. Chunk c handles l in
// [c*13, min(c*13+13, 49)). Partial pooled sums -> g_poolp[c][s][d].
#define CHL 13
__global__ void __launch_bounds__(512)
k_combine(const float* __restrict__ og_, const float* __restrict__ ob_){
    __shared__ float sv[CHL*DD];
    __shared__ float smu[16], srs[16];
    int s = blockIdx.x, chunk = blockIdx.y, d = threadIdx.x;
    int b = s >> 1;
    int e = g_topi[s];
    int l0 = chunk*CHL;
    int nl = (chunk < 3) ? CHL : (LL - 3*CHL);   // 13,13,13,10
    size_t yb = (size_t)(e*BB+b)*KDn*LL*DD;
    for (int t = 0; t < nl; t++){
        int l = l0 + t;
        int i = l/7, j = l - 7*i;
        int lv = j*7 + i;
        float v = g_ys[yb + (0*LL + l       )*DD + d]
                + g_ys[yb + (1*LL + (48-l)  )*DD + d]
                + g_ys[yb + (2*LL + lv      )*DD + d]
                + g_ys[yb + (3*LL + (48-lv) )*DD + d];
        sv[t*DD + d] = v;
    }
    __syncthreads();
    int w = d >> 5, lane = d & 31;
    if (w < nl){
        int t = w;
        float a = 0.f, s2 = 0.f;
        #pragma unroll
        for (int jj = 0; jj < 16; jj++){
            float xv = sv[t*DD + lane + 32*jj];
            a += xv; s2 += xv*xv;
        }
        #pragma unroll
        for (int o = 16; o; o >>= 1){
            a  += __shfl_xor_sync(0xffffffffu, a, o);
            s2 += __shfl_xor_sync(0xffffffffu, s2, o);
        }
        if (lane == 0){
            float mu = a*(1.f/512.f);
            float var = s2*(1.f/512.f) - mu*mu;
            smu[t] = mu;
            srs[t] = rsqrtf(var + 1e-5f);
        }
    }
    __syncthreads();
    float og = og_[e*DD+d], ob = ob_[e*DD+d];
    const float* zrow = g_z + (size_t)(e*BB+b)*LL*DD + d;
    float pooled = 0.f;
    for (int t = 0; t < nl; t++){
        int l = l0 + t;
        float v = sv[t*DD + d];
        float yn = (v - smu[t])*srs[t]*og + ob;
        float z = zrow[l*DD];
        pooled += yn * (z / (1.f + __expf(-z)));
    }
    g_poolp[(chunk*NSLOT + s)*DD + d] = pooled;
}

// ---------------- K8: final pooled LN per slot + top-2 mix + aux -----------
__global__ void __launch_bounds__(512)
k_mix(float* __restrict__ out, int out_size,
      const float* __restrict__ ng_, const float* __restrict__ nb_){
    int b = blockIdx.x, d = threadIdx.x;
    float res = 0.f;
    #pragma unroll 1
    for (int j = 0; j < 2; j++){
        int s = b*2 + j;
        int e = g_topi[s];
        float pooled = (g_poolp[(0*NSLOT + s)*DD + d]
                      + g_poolp[(1*NSLOT + s)*DD + d]
                      + g_poolp[(2*NSLOT + s)*DD + d]
                      + g_poolp[(3*NSLOT + s)*DD + d]) * (1.f/49.f);
        float2 ss = blockReduce2(pooled, pooled*pooled);
        float mu = ss.x*(1.f/512.f);
        float var = ss.y*(1.f/512.f) - mu*mu;
        float rs = rsqrtf(var + 1e-5f);
        float yn = (pooled - mu)*rs*ng_[e*DD+d] + nb_[e*DD+d];
        res += g_topv[s] * yn;
    }
    out[b*DD + d] = res;
    if (b == 0 && d == 0 && out_size > BB*DD) out[BB*DD] = g_aux;
}

// ---------------- launch ----------------------------------------------------
extern "C" void kernel_launch(void* const* d_in, const int* in_sizes, int n_in,
                              void* d_out, int out_size){
    const float* x    = (const float*)d_in[0];
    const float* wg   = (const float*)d_in[1];
    const float* bg   = (const float*)d_in[2];
    const float* ipw  = (const float*)d_in[3];
    const float* ipb  = (const float*)d_in[4];
    const float* cw   = (const float*)d_in[5];
    const float* cb   = (const float*)d_in[6];
    const float* xpw  = (const float*)d_in[7];
    const float* dtw  = (const float*)d_in[8];
    const float* dtb  = (const float*)d_in[9];
    const float* alog = (const float*)d_in[10];
    const float* ds   = (const float*)d_in[11];
    const float* ong  = (const float*)d_in[12];
    const float* onb  = (const float*)d_in[13];
    const float* ng   = (const float*)d_in[14];
    const float* nb   = (const float*)d_in[15];
    float* out = (float*)d_out;

    cudaFuncSetAttribute(k_inproj, cudaFuncAttributeMaxDynamicSharedMemorySize, IP_SMEM);
    cudaFuncSetAttribute(k_xdbl,   cudaFuncAttributeMaxDynamicSharedMemorySize, XD_SMEM_BYTES);

    k_gate    <<<BB, 512>>>(x, wg, bg);
    k_inproj  <<<dim3(NSLOT, 2), 512, IP_SMEM>>>(x, ipw, ipb, cw, cb);
    k_xdbl    <<<NSLOT*KDn, 512, XD_SMEM_BYTES>>>(xpw, dtw, dtb);
    k_scan    <<<NSLOT*KDn, 512>>>(alog, ds);
    k_combine <<<dim3(NSLOT, 4), 512>>>(ong, onb);
    k_mix     <<<BB, 512>>>(out, out_size, ng, nb);
}

// round 14
// speedup vs baseline: 1.8052x; 1.0403x over previous
#include <cuda_runtime.h>
#include <math.h>

// Problem constants
#define EE  4      // experts
#define BB  32     // batch
#define HH  7
#define LL  49     // H*W
#define DD  512    // dim
#define C2  1024   // 2*dim
#define RR  32     // DT_RANK
#define NS  16     // N_STATE
#define KDn 4      // directions
#define NSLOT (BB*2)   // 64 selected (b, expert) slots

// ---------------- scratch (device globals; no allocation allowed) ----------
__device__ float g_z [EE*BB*LL*DD];          // z half of in_proj [e][b][l][d]
__device__ float g_xs[EE*BB*KDn*LL*DD];      // 4-direction scan inputs
__device__ float g_ys[EE*BB*KDn*LL*DD];      // scan outputs
__device__ float g_dt[NSLOT*KDn*LL*DD];      // softplus(dt), slot-indexed
__device__ float g_Bm[NSLOT*KDn*LL*NS];      // B, slot-indexed
__device__ float g_Cm[NSLOT*KDn*LL*NS];      // C, slot-indexed
__device__ float g_poolp[4*NSLOT*DD];        // partial pooled sums per l-chunk
__device__ float g_raw[BB*EE];
__device__ float g_aux;
__device__ int   g_ctr;                      // last-block-done counter (self-reset)
__device__ int   g_topi[NSLOT];              // slot s -> expert  (b = s>>1)
__device__ float g_topv[NSLOT];              // slot s -> gate coeff

// ---------------- f32x2 packed FMA helpers (sm_103a) -----------------------
__device__ __forceinline__ unsigned long long pk2(float lo, float hi){
    unsigned long long r;
    asm("mov.b64 %0, {%1, %2};" : "=l"(r) : "f"(lo), "f"(hi));
    return r;
}
__device__ __forceinline__ void fma2(unsigned long long& d, unsigned long long a, unsigned long long b){
    asm("fma.rn.f32x2 %0, %1, %2, %0;" : "+l"(d) : "l"(a), "l"(b));
}
__device__ __forceinline__ void upk2(unsigned long long v, float& lo, float& hi){
    asm("mov.b64 {%0, %1}, %2;" : "=f"(lo), "=f"(hi) : "l"(v));
}
__device__ __forceinline__ float ex2f(float x){
    float r; asm("ex2.approx.f32 %0, %1;" : "=f"(r) : "f"(x)); return r;
}
__device__ __forceinline__ float lg2f(float x){
    float r; asm("lg2.approx.f32 %0, %1;" : "=f"(r) : "f"(x)); return r;
}

// ---------------- K1: gate softmax + fused top-k/aux (last block) ----------
__global__ void k_gate(const float* __restrict__ x, const float* __restrict__ wg,
                       const float* __restrict__ bg){
    int b = blockIdx.x, tid = threadIdx.x;           // 512 threads, tid = channel
    const float* xb = x + (size_t)b*LL*DD + tid;
    float s = 0.f;
    #pragma unroll 7
    for (int l = 0; l < LL; l++) s += xb[l*DD];
    s *= (1.f/49.f);
    float p0 = s*wg[tid*EE+0], p1 = s*wg[tid*EE+1];
    float p2 = s*wg[tid*EE+2], p3 = s*wg[tid*EE+3];
    #pragma unroll
    for (int o = 16; o; o >>= 1){
        p0 += __shfl_xor_sync(0xffffffffu, p0, o);
        p1 += __shfl_xor_sync(0xffffffffu, p1, o);
        p2 += __shfl_xor_sync(0xffffffffu, p2, o);
        p3 += __shfl_xor_sync(0xffffffffu, p3, o);
    }
    __shared__ float sp[16][4];
    int w = tid >> 5, lane = tid & 31;
    if (lane == 0){ sp[w][0]=p0; sp[w][1]=p1; sp[w][2]=p2; sp[w][3]=p3; }
    __syncthreads();
    if (tid == 0){
        float lg[4];
        for (int e = 0; e < 4; e++){
            float a = bg[e];
            for (int ww = 0; ww < 16; ww++) a += sp[ww][e];
            lg[e] = a;
        }
        float m = fmaxf(fmaxf(lg[0],lg[1]), fmaxf(lg[2],lg[3]));
        float ex[4], se = 0.f;
        for (int e = 0; e < 4; e++){ ex[e] = expf(lg[e]-m); se += ex[e]; }
        for (int e = 0; e < 4; e++) g_raw[b*4+e] = ex[e]/se;
    }
    // ---- last-block-done: run the gate finalization in whichever block
    // finishes last (deterministic result; counter self-resets) ----
    __shared__ int sdone;
    if (tid == 0){
        __threadfence();
        int old = atomicAdd(&g_ctr, 1);
        sdone = (old == BB-1) ? 1 : 0;
    }
    __syncthreads();
    if (sdone){
        __threadfence();
        __shared__ float sraw[32][4];
        __shared__ float smask[32][4];
        __shared__ float sden[4];
        if (tid < 32){
            int bb = tid;
            float r[4];
            #pragma unroll
            for (int e = 0; e < 4; e++){ r[e] = g_raw[bb*4+e]; sraw[bb][e] = r[e]; }
            int i0 = 0; float m0 = r[0];
            #pragma unroll
            for (int e = 1; e < 4; e++) if (r[e] > m0){ m0 = r[e]; i0 = e; }
            int i1 = -1; float m1 = -1e30f;
            #pragma unroll
            for (int e = 0; e < 4; e++) if (e != i0 && r[e] > m1){ m1 = r[e]; i1 = e; }
            #pragma unroll
            for (int e = 0; e < 4; e++) smask[bb][e] = (e==i0 || e==i1) ? 1.f : 0.f;
        }
        __syncthreads();
        if (tid == 0){
            float aux = 0.f;
            for (int e = 0; e < 4; e++){
                float ds = 0.f, imp = 0.f, ld = 0.f;
                for (int bb = 0; bb < 32; bb++){
                    ds  += sraw[bb][e]*smask[bb][e];
                    imp += sraw[bb][e];
                    ld  += smask[bb][e];
                }
                sden[e] = ds + 1e-6f;
                imp *= (1.f/32.f); ld *= (1.f/32.f);
                aux += (ld-imp)*(ld-imp);
            }
            g_aux = 0.01f * aux * 0.25f;
        }
        __syncthreads();
        if (tid < 32){
            int bb = tid;
            float r[4];
            #pragma unroll
            for (int e = 0; e < 4; e++) r[e] = sraw[bb][e];
            int i0 = 0; float m0 = r[0];
            #pragma unroll
            for (int e = 1; e < 4; e++) if (r[e] > m0){ m0 = r[e]; i0 = e; }
            int i1 = -1; float m1 = -1e30f;
            #pragma unroll
            for (int e = 0; e < 4; e++) if (e != i0 && r[e] > m1){ m1 = r[e]; i1 = e; }
            const float cap = 40.f;   // int(1.25*32)
            float s0 = r[i0]*cap/sden[i0];
            float s1 = r[i1]*cap/sden[i1];
            int a0 = i0, a1 = i1; float v0 = s0, v1 = s1;
            if (v1 > v0 || (v1 == v0 && a1 < a0)){
                int t = a0; a0 = a1; a1 = t;
                float tv = v0; v0 = v1; v1 = tv;
            }
            g_topi[bb*2] = a0; g_topi[bb*2+1] = a1;
            g_topv[bb*2] = v0; g_topv[bb*2+1] = v1;
        }
        __syncthreads();
        if (tid == 0) g_ctr = 0;   // reset for next graph replay
    }
}

// ---------------- K3: in_proj GEMM + fused depthwise conv + scatter --------
// grid (64 slots, 2 roles) x 512 threads. sx stored TRANSPOSED in smem
// (sxT[d][l], stride 52). Thread: cth = tid&255 owns 2 cols; lg = tid>>8
// owns l-pairs [lg*26, +26). Role 0 -> xin (smem) + conv; role 1 -> z.
#define SXS 52
#define IP_SMEM ((DD*SXS + LL*DD)*4)   // 106496 + 100352 = 206848
__global__ void __launch_bounds__(512, 1)
k_inproj(const float* __restrict__ x, const float* __restrict__ Wi,
         const float* __restrict__ bi, const float* __restrict__ cw,
         const float* __restrict__ cb){
    extern __shared__ float sm_[];
    float* sxT  = sm_;             // [DD][SXS]
    float* sxin = sm_ + DD*SXS;    // [LL][DD] (role 0 only)
    int s = blockIdx.x, role = blockIdx.y, tid = threadIdx.x;
    int b = s >> 1;
    int e = g_topi[s];
    const float* xb = x + (size_t)b*LL*DD;
    // load + transpose x
    for (int i = tid; i < LL*DD; i += 512){
        int l = i >> 9, d = i & 511;
        sxT[d*SXS + l] = xb[i];
    }
    {
        int d = tid;
        sxT[d*SXS + 49] = 0.f; sxT[d*SXS + 50] = 0.f; sxT[d*SXS + 51] = 0.f;
    }
    __syncthreads();

    int cth = tid & 255, lg = tid >> 8;
    int c0 = cth*2;                      // local col within role's 512
    int lbase = lg*26;
    const float* We = Wi + (size_t)e*DD*C2 + role*DD + c0;
    float2 bia = *(const float2*)(bi + e*C2 + role*DD + c0);
    float* zout = g_z + (size_t)(e*BB+b)*LL*DD;

    unsigned long long acc0[13], acc1[13];
    #pragma unroll
    for (int p = 0; p < 13; p++){ acc0[p] = 0ull; acc1[p] = 0ull; }

    #pragma unroll 8
    for (int kk = 0; kk < DD; kk++){
        float2 w = *(const float2*)(We + (size_t)kk*C2);
        unsigned long long w0 = pk2(w.x, w.x);
        unsigned long long w1 = pk2(w.y, w.y);
        const float* xr = sxT + kk*SXS + lbase;
        #pragma unroll
        for (int p = 0; p < 13; p++){
            unsigned long long xp = *(const unsigned long long*)(xr + 2*p);
            fma2(acc0[p], w0, xp);
            fma2(acc1[p], w1, xp);
        }
    }

    // epilogue: add bias, store (role 0 -> sxin smem, role 1 -> g_z)
    #pragma unroll
    for (int p = 0; p < 13; p++){
        int l0 = lbase + 2*p, l1 = l0 + 1;
        float a00, a01, a10, a11;
        upk2(acc0[p], a00, a01);   // (c0 @ l0, c0 @ l1)
        upk2(acc1[p], a10, a11);   // (c1 @ l0, c1 @ l1)
        if (l0 < LL){
            float2 o = make_float2(a00 + bia.x, a10 + bia.y);
            if (role == 0) *(float2*)(sxin + (size_t)l0*DD + c0) = o;
            else           *(float2*)(zout + (size_t)l0*DD + c0) = o;
        }
        if (l1 < LL){
            float2 o = make_float2(a01 + bia.x, a11 + bia.y);
            if (role == 0) *(float2*)(sxin + (size_t)l1*DD + c0) = o;
            else           *(float2*)(zout + (size_t)l1*DD + c0) = o;
        }
    }
    if (role != 0) return;
    __syncthreads();
    // ---- depthwise 3x3 conv + silu + 4-direction scatter; d = tid ----
    float* xsb = g_xs + (size_t)(e*BB+b)*KDn*LL*DD;
    {
        int d = tid;
        float w9[9];
        #pragma unroll
        for (int t = 0; t < 9; t++) w9[t] = cw[(e*DD+d)*9 + t];
        float bias = cb[e*DD+d];
        float row[3][7];
        #pragma unroll
        for (int j = 0; j < 7; j++){
            row[0][j] = sxin[(0*7+j)*DD + d];
            row[1][j] = sxin[(1*7+j)*DD + d];
        }
        #pragma unroll
        for (int i = 0; i < 7; i++){
            if (i < 6){
                #pragma unroll
                for (int j = 0; j < 7; j++)
                    row[(i+1)%3][j] = sxin[((i+1)*7+j)*DD + d];
            }
            const float* rm = (i > 0) ? row[(i-1)%3] : nullptr;
            const float* rc = row[i%3];
            const float* rp = (i < 6) ? row[(i+1)%3] : nullptr;
            #pragma unroll
            for (int j = 0; j < 7; j++){
                float a = bias;
                #pragma unroll
                for (int dj = 0; dj < 3; dj++){
                    int jj = j + dj - 1;
                    if (jj < 0 || jj > 6) continue;
                    if (i > 0) a += rm[jj]*w9[0*3+dj];
                    a += rc[jj]*w9[1*3+dj];
                    if (i < 6) a += rp[jj]*w9[2*3+dj];
                }
                float v = a / (1.f + __expf(-a));   // silu
                int l  = i*7 + j;
                int lv = j*7 + i;
                xsb[(0*LL + l       )*DD + d] = v;
                xsb[(1*LL + (48-l)  )*DD + d] = v;
                xsb[(2*LL + lv      )*DD + d] = v;
                xsb[(3*LL + (48-lv) )*DD + d] = v;
            }
        }
    }
}

// ---------------- K5a: x_dbl GEMM + dt_proj GEMM + softplus ----------------
// grid = 64 slots x 4 k = 256 blocks, 512 threads. Writes g_dt (softplus'd),
// g_Bm, g_Cm.
#define DTW_S 513
#define XD_SMEM_BYTES ((LL*DD + 64*DD)*4)   // 100352 + 131072 = 231424
__global__ void __launch_bounds__(512, 1)
k_xdbl(const float* __restrict__ xpw_, const float* __restrict__ dtw_,
       const float* __restrict__ dtb_){
    extern __shared__ float sm[];
    float* sx  = sm;                 // LL*DD floats
    float* wsm = sm + LL*DD;         // 64 x 512, XOR-swizzled (phase A)
    float* dtwT = sm + LL*DD;        // 32 x DTW_S (phase B) aliases wsm
    float* sdbl = dtwT + 32*DTW_S;   // 49 x 32 dt-rank
    float* sBC  = sdbl + LL*32;      // 49 x 32 (B | C)
    int idx = blockIdx.x;
    int k = idx & 3, s = idx >> 2;
    int b = s >> 1;
    int e = g_topi[s];
    int tid = threadIdx.x;
    int lane = tid & 31, w = tid >> 5;

    const float* xsrow = g_xs + (size_t)((e*BB+b)*KDn + k)*LL*DD;
    const float* xpw = xpw_ + (size_t)((e*KDn+k)*64)*DD;   // [c][d]
    const float* dtw = dtw_ + (size_t)((e*KDn+k)*DD)*RR;   // [d][r]
    const float* dtb = dtb_ + (e*KDn+k)*DD;
    size_t skbase = (size_t)(s*KDn + k);
    float* dtout = g_dt + skbase*LL*DD;
    float* Bout  = g_Bm + skbase*LL*NS;
    float* Cout  = g_Cm + skbase*LL*NS;

    // load sx tile (coalesced) + xpw into XOR-swizzled smem
    for (int i = tid; i < LL*DD; i += 512) sx[i] = xsrow[i];
    for (int i = tid; i < 64*DD; i += 512){
        int c = i >> 9, dd = i & 511;
        int g = dd >> 2;
        wsm[c*DD + ((((g ^ (c & 7)) << 2)) | (dd & 3))] = xpw[i];
    }
    __syncthreads();

    // ---- Phase A: x_dbl[c][l] = sum_d sx[l][d]*w[c][d], split-K ----
    int wg = w & 7;            // l-group: wg*6..wg*6+5 (wg==0 also handles l=48)
    int ks = w >> 3;           // K-split half
    int kk0 = ks << 8;
    int l0 = wg*6;
    int nl = (wg == 0) ? 7 : 6;
    int c0 = lane, c1 = lane + 32;
    unsigned long long a0[7], a1[7];
    #pragma unroll
    for (int j = 0; j < 7; j++){ a0[j] = 0ull; a1[j] = 0ull; }
    const float* w0base = wsm + c0*DD;
    const float* w1base = wsm + c1*DD;
    int sw = (lane & 7) << 2;     // xor pattern
    #pragma unroll 4
    for (int t = 0; t < 64; t++){
        int kk = kk0 + t*4;
        float4 w0 = *(const float4*)(w0base + (kk ^ sw));
        float4 w1 = *(const float4*)(w1base + (kk ^ sw));
        unsigned long long w0a = pk2(w0.x, w0.y), w0b = pk2(w0.z, w0.w);
        unsigned long long w1a = pk2(w1.x, w1.y), w1b = pk2(w1.z, w1.w);
        #pragma unroll
        for (int j = 0; j < 7; j++){
            if (j < nl){
                int l = (j == 6) ? 48 : (l0 + j);
                float4 xv = *(const float4*)(sx + l*DD + kk);
                unsigned long long xa = pk2(xv.x, xv.y), xb = pk2(xv.z, xv.w);
                fma2(a0[j], w0a, xa); fma2(a0[j], w0b, xb);
                fma2(a1[j], w1a, xa); fma2(a1[j], w1b, xb);
            }
        }
    }
    __syncthreads();   // all wsm/sx phase-A reads done; wsm region reusable

    // stage: split-K half 0 writes, half 1 adds
    if (ks == 0){
        #pragma unroll
        for (int j = 0; j < 7; j++){
            if (j < nl){
                int l = (j == 6) ? 48 : (l0 + j);
                float lo, hi;
                upk2(a0[j], lo, hi); sdbl[l*32 + lane] = lo + hi;
                upk2(a1[j], lo, hi); sBC [l*32 + lane] = lo + hi;
            }
        }
    }
    __syncthreads();
    if (ks == 1){
        #pragma unroll
        for (int j = 0; j < 7; j++){
            if (j < nl){
                int l = (j == 6) ? 48 : (l0 + j);
                float lo, hi;
                upk2(a0[j], lo, hi); sdbl[l*32 + lane] += lo + hi;
                upk2(a1[j], lo, hi); sBC [l*32 + lane] += lo + hi;
            }
        }
    }
    // load dtw transposed into dtwT (disjoint from sdbl/sBC)
    for (int i = tid; i < DD*RR; i += 512){
        int dd = i >> 5, r = i & 31;
        dtwT[r*DTW_S + dd] = dtw[i];
    }
    __syncthreads();

    // write B/C to global
    for (int i = tid; i < LL*NS; i += 512){
        int l = i >> 4, n = i & 15;
        Bout[i] = sBC[l*32 + n];
        Cout[i] = sBC[l*32 + 16 + n];
    }

    // ---- dt projection + softplus; thread dd = tid ----
    int dd = tid;
    float bias = dtb[dd];
    const float L2E = 1.44269504088896f;
    const float LN2 = 0.69314718055995f;
    #pragma unroll 1
    for (int lg = 0; lg < 13; lg++){
        int l0b = lg*4;
        int nlb = (lg < 12) ? 4 : 1;
        float q0 = bias, q1 = bias, q2 = bias, q3 = bias;
        const float4* s0 = (const float4*)(sdbl + (l0b    )*32);
        const float4* s1 = (const float4*)(sdbl + (l0b + 1)*32);
        const float4* s2 = (const float4*)(sdbl + (l0b + 2)*32);
        const float4* s3 = (const float4*)(sdbl + (l0b + 3)*32);
        if (nlb == 4){
            #pragma unroll
            for (int rc = 0; rc < 8; rc++){
                float w0 = dtwT[(4*rc+0)*DTW_S + dd];
                float w1 = dtwT[(4*rc+1)*DTW_S + dd];
                float w2 = dtwT[(4*rc+2)*DTW_S + dd];
                float w3 = dtwT[(4*rc+3)*DTW_S + dd];
                float4 v0 = s0[rc], v1 = s1[rc], v2 = s2[rc], v3 = s3[rc];
                q0 += v0.x*w0 + v0.y*w1 + v0.z*w2 + v0.w*w3;
                q1 += v1.x*w0 + v1.y*w1 + v1.z*w2 + v1.w*w3;
                q2 += v2.x*w0 + v2.y*w1 + v2.z*w2 + v2.w*w3;
                q3 += v3.x*w0 + v3.y*w1 + v3.z*w2 + v3.w*w3;
            }
        } else {
            #pragma unroll
            for (int rc = 0; rc < 8; rc++){
                float w0 = dtwT[(4*rc+0)*DTW_S + dd];
                float w1 = dtwT[(4*rc+1)*DTW_S + dd];
                float w2 = dtwT[(4*rc+2)*DTW_S + dd];
                float w3 = dtwT[(4*rc+3)*DTW_S + dd];
                float4 v0 = s0[rc];
                q0 += v0.x*w0 + v0.y*w1 + v0.z*w2 + v0.w*w3;
            }
        }
        float dts[4] = {q0, q1, q2, q3};
        #pragma unroll
        for (int j = 0; j < 4; j++){
            if (j >= nlb) break;
            float a = dts[j];
            float dtv = fmaxf(a, 0.f) + LN2*lg2f(1.f + ex2f(-fabsf(a)*L2E));
            dtout[(l0b + j)*DD + dd] = dtv;
        }
    }
}

// ---------------- K5b: selective scan (lean; 2 blocks/SM) ------------------
// grid = 256 blocks (s,k), 512 threads, thread = channel dd.
// B/C read via float4 (8 LDS.128/step vs 32 scalar) — issue diet.
__global__ void __launch_bounds__(512, 2)
k_scan(const float* __restrict__ alog_, const float* __restrict__ ds_){
    __shared__ __align__(16) float sB[LL*NS];
    __shared__ __align__(16) float sC[LL*NS];
    int idx = blockIdx.x;
    int k = idx & 3, s = idx >> 2;
    int b = s >> 1;
    int e = g_topi[s];
    int dd = threadIdx.x;
    size_t skbase = (size_t)(s*KDn + k);
    {
        const float* Bg = g_Bm + skbase*LL*NS;
        const float* Cg = g_Cm + skbase*LL*NS;
        for (int i = dd; i < LL*NS; i += 512){ sB[i] = Bg[i]; sC[i] = Cg[i]; }
    }
    float A[NS];
    {
        const float4* al = (const float4*)(alog_ + ((size_t)((e*KDn+k)*DD) + dd)*NS);
        const float L2E = 1.44269504088896f;
        #pragma unroll
        for (int q = 0; q < 4; q++){
            float4 v = al[q];
            A[q*4+0] = -__expf(v.x)*L2E; A[q*4+1] = -__expf(v.y)*L2E;
            A[q*4+2] = -__expf(v.z)*L2E; A[q*4+3] = -__expf(v.w)*L2E;
        }
    }
    float Dd = ds_[(e*KDn+k)*DD + dd];
    const float* dtp = g_dt + skbase*LL*DD + dd;
    const float* xsp = g_xs + (size_t)((e*BB+b)*KDn + k)*LL*DD + dd;
    float*       ysp = g_ys + (size_t)((e*BB+b)*KDn + k)*LL*DD + dd;
    __syncthreads();
    float h[NS];
    #pragma unroll
    for (int n = 0; n < NS; n++) h[n] = 0.f;
    float dtc = dtp[0], xvc = xsp[0];
    const float* dtn_p = dtp + DD;
    const float* xvn_p = xsp + DD;
    const float4* B4 = (const float4*)sB;
    const float4* C4 = (const float4*)sC;
    #pragma unroll 1
    for (int l = 0; l < LL; l++){
        float dtn = 0.f, xvn = 0.f;
        if (l < LL-1){
            dtn = *dtn_p; xvn = *xvn_p;
            dtn_p += DD;  xvn_p += DD;
        }
        float dx = dtc*xvc;
        float y = 0.f;
        #pragma unroll
        for (int q = 0; q < 4; q++){
            float4 Bv = B4[l*4 + q];
            float4 Cv = C4[l*4 + q];
            h[4*q+0] = h[4*q+0]*ex2f(dtc*A[4*q+0]) + dx*Bv.x;  y += h[4*q+0]*Cv.x;
            h[4*q+1] = h[4*q+1]*ex2f(dtc*A[4*q+1]) + dx*Bv.y;  y += h[4*q+1]*Cv.y;
            h[4*q+2] = h[4*q+2]*ex2f(dtc*A[4*q+2]) + dx*Bv.z;  y += h[4*q+2]*Cv.z;
            h[4*q+3] = h[4*q+3]*ex2f(dtc*A[4*q+3]) + dx*Bv.w;  y += h[4*q+3]*Cv.w;
        }
        *ysp = y + Dd*xvc;
        ysp += DD;
        dtc = dtn; xvc = xvn;
    }
}

// ---------------- block reduction (sum, sumsq) over 512 threads ------------
__device__ __forceinline__ float2 blockReduce2(float a, float b){
    __shared__ float sa[16], sb[16];
    __shared__ float2 res;
    int lane = threadIdx.x & 31, w = threadIdx.x >> 5;
    #pragma unroll
    for (int o = 16; o; o >>= 1){
        a += __shfl_xor_sync(0xffffffffu, a, o);
        b += __shfl_xor_sync(0xffffffffu, b, o);
    }
    __syncthreads();
    if (lane == 0){ sa[w] = a; sb[w] = b; }
    __syncthreads();
    if (w == 0){
        a = (lane < 16) ? sa[lane] : 0.f;
        b = (lane < 16) ? sb[lane] : 0.f;
        #pragma unroll
        for (int o = 8; o; o >>= 1){
            a += __shfl_xor_sync(0xffffffffu, a, o);
            b += __shfl_xor_sync(0xffffffffu, b, o);
        }
        if (lane == 0){ res.x = a; res.y = b; }
    }
    __syncthreads();
    return res;
}

// ---------------- K7: combine dirs + LN + silu(z) gate, CHUNKED over l -----
// grid (64 slots, 4 chunks) x 512 threads. Chunk c handles l in
// [c*13, min(c*13+13, 49)). Partial pooled sums -> g_poolp[c][s][d].
#define CHL 13
__global__ void __launch_bounds__(512)
k_combine(const float* __restrict__ og_, const float* __restrict__ ob_){
    __shared__ float sv[CHL*DD];
    __shared__ float smu[16], srs[16];
    int s = blockIdx.x, chunk = blockIdx.y, d = threadIdx.x;
    int b = s >> 1;
    int e = g_topi[s];
    int l0 = chunk*CHL;
    int nl = (chunk < 3) ? CHL : (LL - 3*CHL);   // 13,13,13,10
    size_t yb = (size_t)(e*BB+b)*KDn*LL*DD;
    for (int t = 0; t < nl; t++){
        int l = l0 + t;
        int i = l/7, j = l - 7*i;
        int lv = j*7 + i;
        float v = g_ys[yb + (0*LL + l       )*DD + d]
                + g_ys[yb + (1*LL + (48-l)  )*DD + d]
                + g_ys[yb + (2*LL + lv      )*DD + d]
                + g_ys[yb + (3*LL + (48-lv) )*DD + d];
        sv[t*DD + d] = v;
    }
    __syncthreads();
    int w = d >> 5, lane = d & 31;
    if (w < nl){
        int t = w;
        float a = 0.f, s2 = 0.f;
        #pragma unroll
        for (int jj = 0; jj < 16; jj++){
            float xv = sv[t*DD + lane + 32*jj];
            a += xv; s2 += xv*xv;
        }
        #pragma unroll
        for (int o = 16; o; o >>= 1){
            a  += __shfl_xor_sync(0xffffffffu, a, o);
            s2 += __shfl_xor_sync(0xffffffffu, s2, o);
        }
        if (lane == 0){
            float mu = a*(1.f/512.f);
            float var = s2*(1.f/512.f) - mu*mu;
            smu[t] = mu;
            srs[t] = rsqrtf(var + 1e-5f);
        }
    }
    __syncthreads();
    float og = og_[e*DD+d], ob = ob_[e*DD+d];
    const float* zrow = g_z + (size_t)(e*BB+b)*LL*DD + d;
    float pooled = 0.f;
    for (int t = 0; t < nl; t++){
        int l = l0 + t;
        float v = sv[t*DD + d];
        float yn = (v - smu[t])*srs[t]*og + ob;
        float z = zrow[l*DD];
        pooled += yn * (z / (1.f + __expf(-z)));
    }
    g_poolp[(chunk*NSLOT + s)*DD + d] = pooled;
}

// ---------------- K8: final pooled LN per slot + top-2 mix + aux -----------
__global__ void __launch_bounds__(512)
k_mix(float* __restrict__ out, int out_size,
      const float* __restrict__ ng_, const float* __restrict__ nb_){
    int b = blockIdx.x, d = threadIdx.x;
    float res = 0.f;
    #pragma unroll 1
    for (int j = 0; j < 2; j++){
        int s = b*2 + j;
        int e = g_topi[s];
        float pooled = (g_poolp[(0*NSLOT + s)*DD + d]
                      + g_poolp[(1*NSLOT + s)*DD + d]
                      + g_poolp[(2*NSLOT + s)*DD + d]
                      + g_poolp[(3*NSLOT + s)*DD + d]) * (1.f/49.f);
        float2 ss = blockReduce2(pooled, pooled*pooled);
        float mu = ss.x*(1.f/512.f);
        float var = ss.y*(1.f/512.f) - mu*mu;
        float rs = rsqrtf(var + 1e-5f);
        float yn = (pooled - mu)*rs*ng_[e*DD+d] + nb_[e*DD+d];
        res += g_topv[s] * yn;
    }
    out[b*DD + d] = res;
    if (b == 0 && d == 0 && out_size > BB*DD) out[BB*DD] = g_aux;
}

// ---------------- launch ----------------------------------------------------
extern "C" void kernel_launch(void* const* d_in, const int* in_sizes, int n_in,
                              void* d_out, int out_size){
    const float* x    = (const float*)d_in[0];
    const float* wg   = (const float*)d_in[1];
    const float* bg   = (const float*)d_in[2];
    const float* ipw  = (const float*)d_in[3];
    const float* ipb  = (const float*)d_in[4];
    const float* cw   = (const float*)d_in[5];
    const float* cb   = (const float*)d_in[6];
    const float* xpw  = (const float*)d_in[7];
    const float* dtw  = (const float*)d_in[8];
    const float* dtb  = (const float*)d_in[9];
    const float* alog = (const float*)d_in[10];
    const float* ds   = (const float*)d_in[11];
    const float* ong  = (const float*)d_in[12];
    const float* onb  = (const float*)d_in[13];
    const float* ng   = (const float*)d_in[14];
    const float* nb   = (const float*)d_in[15];
    float* out = (float*)d_out;

    cudaFuncSetAttribute(k_inproj, cudaFuncAttributeMaxDynamicSharedMemorySize, IP_SMEM);
    cudaFuncSetAttribute(k_xdbl,   cudaFuncAttributeMaxDynamicSharedMemorySize, XD_SMEM_BYTES);

    k_gate    <<<BB, 512>>>(x, wg, bg);
    k_inproj  <<<dim3(NSLOT, 2), 512, IP_SMEM>>>(x, ipw, ipb, cw, cb);
    k_xdbl    <<<NSLOT*KDn, 512, XD_SMEM_BYTES>>>(xpw, dtw, dtb);
    k_scan    <<<NSLOT*KDn, 512>>>(alog, ds);
    k_combine <<<dim3(NSLOT, 4), 512>>>(ong, onb);
    k_mix     <<<BB, 512>>>(out, out_size, ng, nb);
}